// round 7
// baseline (speedup 1.0000x reference)
#include <cuda_runtime.h>
#include <cstdint>
#include <cstddef>

#define NN   50000
#define EE   600000
#define DD   128
#define OUTD 64
#define NB   ((NN + 255) / 256)   // 196 scan blocks

// ---------------------------------------------------------------------------
// Scratch state (no allocations allowed -> __device__ globals)
// ---------------------------------------------------------------------------
__device__ int   g_counts[NN];
__device__ int   g_cursor[NN];
__device__ int   g_rowoff[NN + 1];
__device__ int   g_bsum[NB];
__device__ int   g_csrsrc[EE];
__device__ float g_deg[NN];
__device__ float g_sdeg[NN];
__device__ float g_bufA[(size_t)NN * DD];
__device__ float g_bufB[(size_t)NN * DD];
__device__ float g_bW1[DD];
__device__ float g_bW2[DD];
__device__ float2 g_Whl1[DD * DD];    // split(W1@W1): (tf32-hi, tf32-lo)
__device__ float2 g_Whl2[DD * DD];    // split(W2@W2)
__device__ float2 g_WhlO[DD * OUTD];  // split(Wout)
__device__ int   g_is32;

// ---------------------------------------------------------------------------
// tf32 split + mma helpers
// ---------------------------------------------------------------------------
__device__ __forceinline__ void split_tf32(float x, unsigned& hi, unsigned& lo) {
    unsigned h;
    asm("cvt.rna.tf32.f32 %0, %1;" : "=r"(h) : "f"(x));
    float r = x - __uint_as_float(h);
    unsigned l;
    asm("cvt.rna.tf32.f32 %0, %1;" : "=r"(l) : "f"(r));
    hi = h; lo = l;
}

__device__ __forceinline__ void mma_tf32(float c[4], const unsigned a[4],
                                         unsigned b0, unsigned b1) {
    asm volatile(
        "mma.sync.aligned.m16n8k8.row.col.f32.tf32.tf32.f32 "
        "{%0,%1,%2,%3}, {%4,%5,%6,%7}, {%8,%9}, {%0,%1,%2,%3};"
        : "+f"(c[0]), "+f"(c[1]), "+f"(c[2]), "+f"(c[3])
        : "r"(a[0]), "r"(a[1]), "r"(a[2]), "r"(a[3]), "r"(b0), "r"(b1));
}

// Shared 3xTF32 mainloop over a 128-row A tile (stride 132 floats) and a
// split-W smem tile (float2, stride WS). Warp covers rows [r0, r0+16).
template <int NT, int WS>
__device__ __forceinline__ void tc_mainloop(const float* Asm, const float2* Wsm,
                                            int r0, int gid, int tig,
                                            float (*c)[4]) {
    for (int ks = 0; ks < 16; ++ks) {
        int k0 = ks * 8;
        float a0f = Asm[(r0 + gid) * 132 + k0 + tig];
        float a1f = Asm[(r0 + gid + 8) * 132 + k0 + tig];
        float a2f = Asm[(r0 + gid) * 132 + k0 + tig + 4];
        float a3f = Asm[(r0 + gid + 8) * 132 + k0 + tig + 4];
        unsigned ah[4], al[4];
        split_tf32(a0f, ah[0], al[0]);
        split_tf32(a1f, ah[1], al[1]);
        split_tf32(a2f, ah[2], al[2]);
        split_tf32(a3f, ah[3], al[3]);
        const float2* W0 = Wsm + (k0 + tig) * WS;
        const float2* W1 = Wsm + (k0 + tig + 4) * WS;
        #pragma unroll
        for (int nt = 0; nt < NT; ++nt) {
            float2 b0 = W0[nt * 8 + gid];
            float2 b1 = W1[nt * 8 + gid];
            unsigned bh0 = __float_as_uint(b0.x), bl0 = __float_as_uint(b0.y);
            unsigned bh1 = __float_as_uint(b1.x), bl1 = __float_as_uint(b1.y);
            mma_tf32(c[nt], ah, bh0, bh1);   // Ah*Wh
            mma_tf32(c[nt], al, bh0, bh1);   // Al*Wh
            mma_tf32(c[nt], ah, bl0, bl1);   // Ah*Wl
        }
    }
}

// Gather 128 aggregated rows into the A smem tile. 8 warps x 16 nodes each,
// warp-per-node, lane owns one float4 of the 128-col row. Rows >= NN -> 0.
__device__ __forceinline__ void gather_tile(const float* __restrict__ in,
                                            float* Asm, int row0) {
    const int warp = threadIdx.x >> 5, lane = threadIdx.x & 31;
    const float4* base = (const float4*)in;
    #pragma unroll 1
    for (int t = 0; t < 16; ++t) {
        int lr = warp * 16 + t;
        int node = row0 + lr;
        float4 acc = make_float4(0.f, 0.f, 0.f, 0.f);
        if (node < NN) {
            int beg = g_rowoff[node], end = g_rowoff[node + 1];
            int e = beg;
            for (; e + 4 <= end; e += 4) {
                int s0 = g_csrsrc[e];
                int s1 = g_csrsrc[e + 1];
                int s2 = g_csrsrc[e + 2];
                int s3 = g_csrsrc[e + 3];
                float4 v0 = base[(size_t)s0 * 32 + lane];
                float4 v1 = base[(size_t)s1 * 32 + lane];
                float4 v2 = base[(size_t)s2 * 32 + lane];
                float4 v3 = base[(size_t)s3 * 32 + lane];
                acc.x += (v0.x + v1.x) + (v2.x + v3.x);
                acc.y += (v0.y + v1.y) + (v2.y + v3.y);
                acc.z += (v0.z + v1.z) + (v2.z + v3.z);
                acc.w += (v0.w + v1.w) + (v2.w + v3.w);
            }
            for (; e < end; ++e) {
                int s0 = g_csrsrc[e];
                float4 v0 = base[(size_t)s0 * 32 + lane];
                acc.x += v0.x; acc.y += v0.y; acc.z += v0.z; acc.w += v0.w;
            }
        }
        *(float4*)(Asm + lr * 132 + lane * 4) = acc;
    }
}

// ---------------------------------------------------------------------------
// Setup kernels
// ---------------------------------------------------------------------------
__global__ void k_init() {
    int i = blockIdx.x * blockDim.x + threadIdx.x;
    if (i < NN) { g_counts[i] = 0; g_cursor[i] = 0; }
    if (i == 0) g_is32 = 0;
}

__global__ void k_detect(const int* __restrict__ w) {
    int i = blockIdx.x * blockDim.x + threadIdx.x;
    if (i < 4096) {
        if (w[2 * i + 1] != 0) g_is32 = 1;
    }
}

__device__ __forceinline__ int load_edge(const void* ei, int idx, int is32) {
    if (is32) return ((const int*)ei)[idx];
    return (int)((const long long*)ei)[idx];
}

__global__ void k_count(const void* __restrict__ ei) {
    int e = blockIdx.x * blockDim.x + threadIdx.x;
    if (e >= EE) return;
    int is32 = g_is32;
    int dst = load_edge(ei, EE + e, is32);
    if ((unsigned)dst < (unsigned)NN)
        atomicAdd(&g_counts[dst], 1);
}

__global__ void k_bsum() {
    __shared__ int ws[8];
    int tid = threadIdx.x;
    int i = blockIdx.x * 256 + tid;
    int v = (i < NN) ? g_counts[i] : 0;
    #pragma unroll
    for (int o = 16; o > 0; o >>= 1) v += __shfl_down_sync(0xffffffffu, v, o);
    if ((tid & 31) == 0) ws[tid >> 5] = v;
    __syncthreads();
    if (tid == 0) {
        int s = 0;
        #pragma unroll
        for (int w = 0; w < 8; ++w) s += ws[w];
        g_bsum[blockIdx.x] = s;
    }
}

// Each block redundantly reduces g_bsum[0..blockIdx-1] for its prefix (196
// ints), then does the local scan. Replaces the separate k_bscan launch.
__global__ void k_rowoff() {
    __shared__ int ws[8];
    __shared__ int s_prefix;
    int tid = threadIdx.x;
    int lane = tid & 31, wid = tid >> 5;

    // cross-block exclusive prefix (blockIdx.x <= 195 < 256)
    int p = (tid < blockIdx.x) ? g_bsum[tid] : 0;
    #pragma unroll
    for (int o = 16; o > 0; o >>= 1) p += __shfl_down_sync(0xffffffffu, p, o);
    if (lane == 0) ws[wid] = p;
    __syncthreads();
    if (tid == 0) {
        int s = 0;
        #pragma unroll
        for (int w = 0; w < 8; ++w) s += ws[w];
        s_prefix = s;
    }
    __syncthreads();
    int prefix = s_prefix;
    __syncthreads();

    // local scan of counts
    int i = blockIdx.x * 256 + tid;
    int v = (i < NN) ? g_counts[i] : 0;
    int x = v;
    #pragma unroll
    for (int o = 1; o < 32; o <<= 1) {
        int t = __shfl_up_sync(0xffffffffu, x, o);
        if (lane >= o) x += t;
    }
    if (lane == 31) ws[wid] = x;
    __syncthreads();
    if (wid == 0) {
        int y = (lane < 8) ? ws[lane] : 0;
        #pragma unroll
        for (int o = 1; o < 8; o <<= 1) {
            int t = __shfl_up_sync(0xffffffffu, y, o);
            if (lane >= o) y += t;
        }
        if (lane < 8) ws[lane] = y;
    }
    __syncthreads();
    int excl = x - v + (wid ? ws[wid - 1] : 0) + prefix;
    if (i < NN) {
        g_rowoff[i] = excl;
        g_deg[i] = (float)v;
        if (i == NN - 1) g_rowoff[NN] = excl + v;
    }
}

__global__ void k_fill(const void* __restrict__ ei) {
    int e = blockIdx.x * blockDim.x + threadIdx.x;
    if (e >= EE) return;
    int is32 = g_is32;
    int src = load_edge(ei, e, is32);
    int dst = load_edge(ei, EE + e, is32);
    if ((unsigned)dst >= (unsigned)NN) return;
    if ((unsigned)src >= (unsigned)NN) src = 0;
    int pos = g_rowoff[dst] + atomicAdd(&g_cursor[dst], 1);
    g_csrsrc[pos] = src;
}

__global__ void k_sdeg() {
    int i = blockIdx.x * blockDim.x + threadIdx.x;
    if (i >= NN) return;
    int beg = g_rowoff[i], end = g_rowoff[i + 1];
    float s = 0.f;
    for (int e = beg; e < end; ++e) s += g_deg[g_csrsrc[e]];
    g_sdeg[i] = s;
}

// Wsq = W@W computed and tf32-split in one pass (raw Wsq never materialized)
__global__ void k_matsq_split(const float* __restrict__ W, float2* __restrict__ O) {
    int idx = blockIdx.x * blockDim.x + threadIdx.x;
    if (idx >= DD * DD) return;
    int r = idx >> 7, c = idx & 127;
    float s = 0.f;
    #pragma unroll 8
    for (int k = 0; k < DD; ++k) s += W[r * DD + k] * W[k * DD + c];
    unsigned h, l;
    split_tf32(s, h, l);
    O[idx] = make_float2(__uint_as_float(h), __uint_as_float(l));
}

__global__ void k_wsplit(const float* __restrict__ W, float2* __restrict__ O, int n) {
    int i = blockIdx.x * blockDim.x + threadIdx.x;
    if (i >= n) return;
    unsigned h, l;
    split_tf32(W[i], h, l);
    O[i] = make_float2(__uint_as_float(h), __uint_as_float(l));
}

__global__ void k_bw(const float* __restrict__ b, const float* __restrict__ W,
                     float* __restrict__ bw) {
    int c = threadIdx.x;
    if (c >= DD) return;
    float s = 0.f;
    #pragma unroll 8
    for (int k = 0; k < DD; ++k) s += b[k] * W[k * DD + c];
    bw[c] = s;
}

// ---------------------------------------------------------------------------
// Standalone aggregation (pass 1 of each pool block)
// ---------------------------------------------------------------------------
__global__ void __launch_bounds__(256) k_agg(const float* __restrict__ in,
                                             float* __restrict__ out) {
    int w = (blockIdx.x * blockDim.x + threadIdx.x) >> 5;
    int lane = threadIdx.x & 31;
    if (w >= NN) return;
    int beg = g_rowoff[w], end = g_rowoff[w + 1];
    const float4* base = (const float4*)in;
    float4 acc = make_float4(0.f, 0.f, 0.f, 0.f);
    int e = beg;
    for (; e + 4 <= end; e += 4) {
        int s0 = g_csrsrc[e];
        int s1 = g_csrsrc[e + 1];
        int s2 = g_csrsrc[e + 2];
        int s3 = g_csrsrc[e + 3];
        float4 v0 = base[(size_t)s0 * 32 + lane];
        float4 v1 = base[(size_t)s1 * 32 + lane];
        float4 v2 = base[(size_t)s2 * 32 + lane];
        float4 v3 = base[(size_t)s3 * 32 + lane];
        acc.x += (v0.x + v1.x) + (v2.x + v3.x);
        acc.y += (v0.y + v1.y) + (v2.y + v3.y);
        acc.z += (v0.z + v1.z) + (v2.z + v3.z);
        acc.w += (v0.w + v1.w) + (v2.w + v3.w);
    }
    for (; e < end; ++e) {
        int s0 = g_csrsrc[e];
        float4 v0 = base[(size_t)s0 * 32 + lane];
        acc.x += v0.x; acc.y += v0.y; acc.z += v0.z; acc.w += v0.w;
    }
    ((float4*)out)[(size_t)w * 32 + lane] = acc;
}

// ---------------------------------------------------------------------------
// Fused: gather(agg pass 2) + pool GEMM  ->  h = relu(A(in)@Wsq + s*bw + d*bv)
// ---------------------------------------------------------------------------
__global__ void __launch_bounds__(256, 1)
k_fused_ag(const float* __restrict__ in, const float2* __restrict__ Whl,
           const float* __restrict__ sv, const float* __restrict__ dv,
           const float* __restrict__ bw, const float* __restrict__ bv,
           float* __restrict__ C) {
    constexpr int WS = 130;
    extern __shared__ char smraw[];
    float*  Asm = (float*)smraw;
    float2* Wsm = (float2*)(smraw + 128 * 132 * sizeof(float));

    const int tid = threadIdx.x;
    const int row0 = blockIdx.x * 128;

    #pragma unroll 4
    for (int idx = tid; idx < 128 * 128; idx += 256) {
        int k = idx >> 7, n = idx & 127;
        Wsm[k * WS + n] = Whl[idx];
    }
    gather_tile(in, Asm, row0);
    __syncthreads();

    const int warp = tid >> 5, lane = tid & 31;
    const int gid = lane >> 2, tig = lane & 3;
    const int r0 = warp * 16;

    float c[16][4];
    #pragma unroll
    for (int nt = 0; nt < 16; ++nt)
        #pragma unroll
        for (int q = 0; q < 4; ++q) c[nt][q] = 0.f;

    tc_mainloop<16, WS>(Asm, Wsm, r0, gid, tig, c);

    int rA = row0 + r0 + gid;
    int rB = rA + 8;
    float sA = 0.f, dA = 0.f, sB = 0.f, dB = 0.f;
    if (rA < NN) { sA = sv[rA]; dA = dv[rA]; }
    if (rB < NN) { sB = sv[rB]; dB = dv[rB]; }
    #pragma unroll
    for (int nt = 0; nt < 16; ++nt) {
        int col = nt * 8 + 2 * tig;
        float v0 = bv[col], v1 = bv[col + 1];
        float w0 = bw[col], w1 = bw[col + 1];
        if (rA < NN) {
            float x0 = fmaxf(c[nt][0] + sA * w0 + dA * v0, 0.f);
            float x1 = fmaxf(c[nt][1] + sA * w1 + dA * v1, 0.f);
            *(float2*)&C[(size_t)rA * DD + col] = make_float2(x0, x1);
        }
        if (rB < NN) {
            float x0 = fmaxf(c[nt][2] + sB * w0 + dB * v0, 0.f);
            float x1 = fmaxf(c[nt][3] + sB * w1 + dB * v1, 0.f);
            *(float2*)&C[(size_t)rB * DD + col] = make_float2(x0, x1);
        }
    }
}

// ---------------------------------------------------------------------------
// Fused: gather(agg pass 4) + pool GEMM2 + relu (into smem) + output GEMM
//   out = relu(A(in)@Wsq2 + s*bw + d*bv) @ Wout + bout
// ---------------------------------------------------------------------------
__global__ void __launch_bounds__(256, 1)
k_fused_ag_out(const float* __restrict__ in, const float2* __restrict__ Whl2,
               const float2* __restrict__ WhlO,
               const float* __restrict__ sv, const float* __restrict__ dv,
               const float* __restrict__ bw, const float* __restrict__ bv,
               const float* __restrict__ bout, float* __restrict__ out) {
    constexpr int WS = 130, WS2 = 66;
    extern __shared__ char smraw[];
    float*  Asm = (float*)smraw;
    float2* Wsm = (float2*)(smraw + 128 * 132 * sizeof(float));

    const int tid = threadIdx.x;
    const int row0 = blockIdx.x * 128;

    #pragma unroll 4
    for (int idx = tid; idx < 128 * 128; idx += 256) {
        int k = idx >> 7, n = idx & 127;
        Wsm[k * WS + n] = Whl2[idx];
    }
    gather_tile(in, Asm, row0);
    __syncthreads();

    const int warp = tid >> 5, lane = tid & 31;
    const int gid = lane >> 2, tig = lane & 3;
    const int r0 = warp * 16;

    float c[16][4];
    #pragma unroll
    for (int nt = 0; nt < 16; ++nt)
        #pragma unroll
        for (int q = 0; q < 4; ++q) c[nt][q] = 0.f;

    tc_mainloop<16, WS>(Asm, Wsm, r0, gid, tig, c);

    __syncthreads();   // everyone finished reading the gathered A tile

    // relu(h) -> Asm (rows >= NN keep their gathered zeros)
    {
        int rA = row0 + r0 + gid;
        int rB = rA + 8;
        float sA = 0.f, dA = 0.f, sB = 0.f, dB = 0.f;
        if (rA < NN) { sA = sv[rA]; dA = dv[rA]; }
        if (rB < NN) { sB = sv[rB]; dB = dv[rB]; }
        #pragma unroll
        for (int nt = 0; nt < 16; ++nt) {
            int col = nt * 8 + 2 * tig;
            float v0 = bv[col], v1 = bv[col + 1];
            float w0 = bw[col], w1 = bw[col + 1];
            if (rA < NN) {
                float x0 = fmaxf(c[nt][0] + sA * w0 + dA * v0, 0.f);
                float x1 = fmaxf(c[nt][1] + sA * w1 + dA * v1, 0.f);
                *(float2*)(Asm + (r0 + gid) * 132 + col) = make_float2(x0, x1);
            }
            if (rB < NN) {
                float x0 = fmaxf(c[nt][2] + sB * w0 + dB * v0, 0.f);
                float x1 = fmaxf(c[nt][3] + sB * w1 + dB * v1, 0.f);
                *(float2*)(Asm + (r0 + gid + 8) * 132 + col) = make_float2(x0, x1);
            }
        }
    }
    // Wout split tile over the (now dead) Wsq2 smem region
    #pragma unroll 4
    for (int idx = tid; idx < 128 * OUTD; idx += 256) {
        int k = idx >> 6, n = idx & 63;
        Wsm[k * WS2 + n] = WhlO[idx];
    }
    __syncthreads();

    float c2[8][4];
    #pragma unroll
    for (int nt = 0; nt < 8; ++nt)
        #pragma unroll
        for (int q = 0; q < 4; ++q) c2[nt][q] = 0.f;

    tc_mainloop<8, WS2>(Asm, Wsm, r0, gid, tig, c2);

    int rA = row0 + r0 + gid;
    int rB = rA + 8;
    #pragma unroll
    for (int nt = 0; nt < 8; ++nt) {
        int col = nt * 8 + 2 * tig;
        float v0 = bout[col], v1 = bout[col + 1];
        if (rA < NN)
            *(float2*)&out[(size_t)rA * OUTD + col] =
                make_float2(c2[nt][0] + v0, c2[nt][1] + v1);
        if (rB < NN)
            *(float2*)&out[(size_t)rB * OUTD + col] =
                make_float2(c2[nt][2] + v0, c2[nt][3] + v1);
    }
}

// ---------------------------------------------------------------------------
// Launch
// ---------------------------------------------------------------------------
extern "C" void kernel_launch(void* const* d_in, const int* in_sizes, int n_in,
                              void* d_out, int out_size) {
    const float* x    = (const float*)d_in[0];
    const void*  ei   = d_in[1];
    const float* W1   = (const float*)d_in[2];
    const float* b1   = (const float*)d_in[3];
    const float* W2   = (const float*)d_in[4];
    const float* b2   = (const float*)d_in[5];
    const float* Wout = (const float*)d_in[6];
    const float* bout = (const float*)d_in[7];
    float* out = (float*)d_out;

    void *pA, *pB, *pbW1, *pbW2, *pdeg, *psdeg, *pWhl1, *pWhl2, *pWhlO;
    cudaGetSymbolAddress(&pA, g_bufA);
    cudaGetSymbolAddress(&pB, g_bufB);
    cudaGetSymbolAddress(&pbW1, g_bW1);
    cudaGetSymbolAddress(&pbW2, g_bW2);
    cudaGetSymbolAddress(&pdeg, g_deg);
    cudaGetSymbolAddress(&psdeg, g_sdeg);
    cudaGetSymbolAddress(&pWhl1, g_Whl1);
    cudaGetSymbolAddress(&pWhl2, g_Whl2);
    cudaGetSymbolAddress(&pWhlO, g_WhlO);
    float*  bufA = (float*)pA;
    float*  bufB = (float*)pB;
    float*  bW1  = (float*)pbW1;
    float*  bW2  = (float*)pbW2;
    float*  degv = (float*)pdeg;
    float*  sdeg = (float*)psdeg;
    float2* Whl1 = (float2*)pWhl1;
    float2* Whl2 = (float2*)pWhl2;
    float2* WhlO = (float2*)pWhlO;

    const size_t SMF = 128 * 132 * sizeof(float) + 128 * 130 * sizeof(float2); // 196 KB
    cudaFuncSetAttribute(k_fused_ag,
                         cudaFuncAttributeMaxDynamicSharedMemorySize, (int)SMF);
    cudaFuncSetAttribute(k_fused_ag_out,
                         cudaFuncAttributeMaxDynamicSharedMemorySize, (int)SMF);

    const int GN  = (NN + 255) / 256;
    const int GE  = (EE + 255) / 256;
    const int GAG = (NN * 32 + 255) / 256;       // one warp per node
    const int GGM = (NN + 127) / 128;

    // ---- CSR build + precompute ----
    k_init<<<GN, 256>>>();
    k_detect<<<16, 256>>>((const int*)ei);
    k_count<<<GE, 256>>>(ei);
    k_matsq_split<<<(DD * DD + 255) / 256, 256>>>(W1, Whl1);
    k_matsq_split<<<(DD * DD + 255) / 256, 256>>>(W2, Whl2);
    k_wsplit<<<(DD * OUTD + 255) / 256, 256>>>(Wout, WhlO, DD * OUTD);
    k_bw<<<1, 128>>>(b1, W1, bW1);
    k_bw<<<1, 128>>>(b2, W2, bW2);
    k_bsum<<<NB, 256>>>();
    k_rowoff<<<NB, 256>>>();
    k_fill<<<GE, 256>>>(ei);
    k_sdeg<<<GN, 256>>>();

    // ---- Block 1: h1 = relu(A^2(x) @ W1^2 + s*(b1@W1) + d*b1) ----
    k_agg<<<GAG, 256>>>(x, bufA);
    k_fused_ag<<<GGM, 256, SMF>>>(bufA, Whl1, sdeg, degv, bW1, b1, bufB);

    // ---- Block 2 + output: out = relu(A^2(h1)@W2^2 + ...) @ Wout + bout ----
    k_agg<<<GAG, 256>>>(bufB, bufA);
    k_fused_ag_out<<<GGM, 256, SMF>>>(bufA, Whl2, WhlO, sdeg, degv, bW2, b2,
                                      bout, out);
}

// round 9
// speedup vs baseline: 1.9468x; 1.9468x over previous
#include <cuda_runtime.h>
#include <cuda_fp16.h>
#include <cstdint>
#include <cstddef>
#include <cstring>

#define NN   50000
#define EE   600000
#define DD   128
#define OUTD 64
#define NB   ((NN + 255) / 256)   // 196 scan blocks

// ---------------------------------------------------------------------------
// Scratch state (no allocations allowed -> __device__ globals)
// ---------------------------------------------------------------------------
__device__ int   g_counts[NN];
__device__ int   g_cursor[NN];
__device__ int   g_rowoff[NN + 1];
__device__ int   g_bsum[NB];
__device__ int   g_csrsrc[EE];
__device__ float g_deg[NN];
__device__ float g_sdeg[NN];
__device__ float g_bufA[(size_t)NN * DD];
__device__ float g_bufB[(size_t)NN * DD];
__device__ float g_bW1[DD];
__device__ float g_bW2[DD];
// Weight tiles in k-pair split-fp16 layout: element (p, n) packs
//   .x = half2( hi(W[2p][n]), hi(W[2p+1][n]) )   (bit-cast)
//   .y = half2( lo-residuals )                    (bit-cast)
__device__ float2 g_Wp1[(DD / 2) * DD];    // split(W1@W1)
__device__ float2 g_Wp2[(DD / 2) * DD];    // split(W2@W2)
__device__ float2 g_WpO[(DD / 2) * OUTD];  // split(Wout)
__device__ int   g_is32;

// ---------------------------------------------------------------------------
// helpers
// ---------------------------------------------------------------------------
__device__ __forceinline__ unsigned h2_bits(__half2 h) {
    unsigned u; memcpy(&u, &h, 4); return u;
}

// pack two consecutive-k weights into (hi-pair, lo-pair) bit-cast float2
__device__ __forceinline__ float2 pack_pair(float w0, float w1) {
    __half h0 = __float2half_rn(w0), h1 = __float2half_rn(w1);
    float r0 = w0 - __half2float(h0);
    float r1 = w1 - __half2float(h1);
    __half2 hi = __halves2half2(h0, h1);
    __half2 lo = __floats2half2_rn(r0, r1);
    float2 o;
    o.x = __uint_as_float(h2_bits(hi));
    o.y = __uint_as_float(h2_bits(lo));
    return o;
}

__device__ __forceinline__ void mma_f16(float c[4], unsigned a0, unsigned a1,
                                        unsigned a2, unsigned a3,
                                        unsigned b0, unsigned b1) {
    asm volatile(
        "mma.sync.aligned.m16n8k16.row.col.f32.f16.f16.f32 "
        "{%0,%1,%2,%3}, {%4,%5,%6,%7}, {%8,%9}, {%0,%1,%2,%3};"
        : "+f"(c[0]), "+f"(c[1]), "+f"(c[2]), "+f"(c[3])
        : "r"(a0), "r"(a1), "r"(a2), "r"(a3), "r"(b0), "r"(b1));
}

// split a float2 (two consecutive k) into hi/lo half2 register pair
__device__ __forceinline__ void split2(float2 a, unsigned& hi, unsigned& lo) {
    __half2 h = __floats2half2_rn(a.x, a.y);
    float r0 = a.x - __low2float(h);
    float r1 = a.y - __high2float(h);
    __half2 l = __floats2half2_rn(r0, r1);
    hi = h2_bits(h);
    lo = h2_bits(l);
}

// ---------------------------------------------------------------------------
// Setup kernels
// ---------------------------------------------------------------------------
__global__ void k_init(const int* __restrict__ eiw) {
    int i = blockIdx.x * blockDim.x + threadIdx.x;
    if (i < NN) { g_counts[i] = 0; g_cursor[i] = 0; }
    if (i == 0) g_is32 = 0;
    // int64-vs-int32 detection folded in: int64 little-endian has zero hi words
    if (i < 4096) {
        if (eiw[2 * i + 1] != 0) g_is32 = 1;
    }
}

__device__ __forceinline__ int load_edge(const void* ei, int idx, int is32) {
    if (is32) return ((const int*)ei)[idx];
    return (int)((const long long*)ei)[idx];
}

__global__ void k_count(const void* __restrict__ ei) {
    int e = blockIdx.x * blockDim.x + threadIdx.x;
    if (e >= EE) return;
    int is32 = g_is32;
    int dst = load_edge(ei, EE + e, is32);
    if ((unsigned)dst < (unsigned)NN)
        atomicAdd(&g_counts[dst], 1);
}

__global__ void k_bsum() {
    __shared__ int ws[8];
    int tid = threadIdx.x;
    int i = blockIdx.x * 256 + tid;
    int v = (i < NN) ? g_counts[i] : 0;
    #pragma unroll
    for (int o = 16; o > 0; o >>= 1) v += __shfl_down_sync(0xffffffffu, v, o);
    if ((tid & 31) == 0) ws[tid >> 5] = v;
    __syncthreads();
    if (tid == 0) {
        int s = 0;
        #pragma unroll
        for (int w = 0; w < 8; ++w) s += ws[w];
        g_bsum[blockIdx.x] = s;
    }
}

// Each block redundantly reduces g_bsum[0..blockIdx-1] for its prefix (196
// ints), then does the local scan.
__global__ void k_rowoff() {
    __shared__ int ws[8];
    __shared__ int s_prefix;
    int tid = threadIdx.x;
    int lane = tid & 31, wid = tid >> 5;

    int p = (tid < blockIdx.x) ? g_bsum[tid] : 0;
    #pragma unroll
    for (int o = 16; o > 0; o >>= 1) p += __shfl_down_sync(0xffffffffu, p, o);
    if (lane == 0) ws[wid] = p;
    __syncthreads();
    if (tid == 0) {
        int s = 0;
        #pragma unroll
        for (int w = 0; w < 8; ++w) s += ws[w];
        s_prefix = s;
    }
    __syncthreads();
    int prefix = s_prefix;
    __syncthreads();

    int i = blockIdx.x * 256 + tid;
    int v = (i < NN) ? g_counts[i] : 0;
    int x = v;
    #pragma unroll
    for (int o = 1; o < 32; o <<= 1) {
        int t = __shfl_up_sync(0xffffffffu, x, o);
        if (lane >= o) x += t;
    }
    if (lane == 31) ws[wid] = x;
    __syncthreads();
    if (wid == 0) {
        int y = (lane < 8) ? ws[lane] : 0;
        #pragma unroll
        for (int o = 1; o < 8; o <<= 1) {
            int t = __shfl_up_sync(0xffffffffu, y, o);
            if (lane >= o) y += t;
        }
        if (lane < 8) ws[lane] = y;
    }
    __syncthreads();
    int excl = x - v + (wid ? ws[wid - 1] : 0) + prefix;
    if (i < NN) {
        g_rowoff[i] = excl;
        g_deg[i] = (float)v;
        if (i == NN - 1) g_rowoff[NN] = excl + v;
    }
}

__global__ void k_fill(const void* __restrict__ ei) {
    int e = blockIdx.x * blockDim.x + threadIdx.x;
    if (e >= EE) return;
    int is32 = g_is32;
    int src = load_edge(ei, e, is32);
    int dst = load_edge(ei, EE + e, is32);
    if ((unsigned)dst >= (unsigned)NN) return;
    if ((unsigned)src >= (unsigned)NN) src = 0;
    int pos = g_rowoff[dst] + atomicAdd(&g_cursor[dst], 1);
    g_csrsrc[pos] = src;
}

__global__ void k_sdeg() {
    int i = blockIdx.x * blockDim.x + threadIdx.x;
    if (i >= NN) return;
    int beg = g_rowoff[i], end = g_rowoff[i + 1];
    float s = 0.f;
    for (int e = beg; e < end; ++e) s += g_deg[g_csrsrc[e]];
    g_sdeg[i] = s;
}

// ---------------------------------------------------------------------------
// One-launch weight prep:
//   blocks [0,32)   : Wp1 = pack(W1@W1)    (pair rows 2p,2p+1 share col loads)
//   blocks [32,64)  : Wp2 = pack(W2@W2)
//   blocks [64,80)  : WpO = pack(Wout)
//   block 80        : bW1 = b1@W1
//   block 81        : bW2 = b2@W2
// ---------------------------------------------------------------------------
__global__ void k_prep(const float* __restrict__ W1, const float* __restrict__ W2,
                       const float* __restrict__ Wout,
                       const float* __restrict__ b1, const float* __restrict__ b2) {
    int blk = blockIdx.x;
    int tid = threadIdx.x;
    if (blk < 64) {
        const float* W = (blk < 32) ? W1 : W2;
        float2* O = (blk < 32) ? g_Wp1 : g_Wp2;
        int idx = (blk & 31) * 256 + tid;       // 0..8191
        int pp = idx >> 7, n = idx & 127;       // pair row, col
        int r0 = 2 * pp, r1 = 2 * pp + 1;
        float s0 = 0.f, s1 = 0.f;
        #pragma unroll 8
        for (int k = 0; k < DD; ++k) {
            float wc = W[k * DD + n];
            s0 += W[r0 * DD + k] * wc;
            s1 += W[r1 * DD + k] * wc;
        }
        O[idx] = pack_pair(s0, s1);
    } else if (blk < 80) {
        int idx = (blk - 64) * 256 + tid;       // 0..4095
        int pp = idx >> 6, n = idx & 63;
        float w0 = Wout[(2 * pp) * OUTD + n];
        float w1 = Wout[(2 * pp + 1) * OUTD + n];
        g_WpO[idx] = pack_pair(w0, w1);
    } else {
        const float* b = (blk == 80) ? b1 : b2;
        const float* W = (blk == 80) ? W1 : W2;
        float* bw = (blk == 80) ? g_bW1 : g_bW2;
        if (tid < DD) {
            float s = 0.f;
            #pragma unroll 8
            for (int k = 0; k < DD; ++k) s += b[k] * W[k * DD + tid];
            bw[tid] = s;
        }
    }
}

// ---------------------------------------------------------------------------
// Aggregation: one warp per node, lane owns one float4 of the 128-col row.
// ---------------------------------------------------------------------------
__global__ void __launch_bounds__(256) k_agg(const float* __restrict__ in,
                                             float* __restrict__ out) {
    int w = (blockIdx.x * blockDim.x + threadIdx.x) >> 5;
    int lane = threadIdx.x & 31;
    if (w >= NN) return;
    int beg = g_rowoff[w], end = g_rowoff[w + 1];
    const float4* base = (const float4*)in;
    float4 acc = make_float4(0.f, 0.f, 0.f, 0.f);
    int e = beg;
    for (; e + 4 <= end; e += 4) {
        int s0 = g_csrsrc[e];
        int s1 = g_csrsrc[e + 1];
        int s2 = g_csrsrc[e + 2];
        int s3 = g_csrsrc[e + 3];
        float4 v0 = base[(size_t)s0 * 32 + lane];
        float4 v1 = base[(size_t)s1 * 32 + lane];
        float4 v2 = base[(size_t)s2 * 32 + lane];
        float4 v3 = base[(size_t)s3 * 32 + lane];
        acc.x += (v0.x + v1.x) + (v2.x + v3.x);
        acc.y += (v0.y + v1.y) + (v2.y + v3.y);
        acc.z += (v0.z + v1.z) + (v2.z + v3.z);
        acc.w += (v0.w + v1.w) + (v2.w + v3.w);
    }
    for (; e < end; ++e) {
        int s0 = g_csrsrc[e];
        float4 v0 = base[(size_t)s0 * 32 + lane];
        acc.x += v0.x; acc.y += v0.y; acc.z += v0.z; acc.w += v0.w;
    }
    ((float4*)out)[(size_t)w * 32 + lane] = acc;
}

// ---------------------------------------------------------------------------
// fp16-3x tensor-core GEMM: C[N x NCOL] = A[N x 128] @ W[128 x NCOL]
//   POOL=true : C = relu(A@W + s_r * bw[c] + d_r * bv[c])
//   POOL=false: C = A@W + bv[c]
// Tile: 64 rows x NCOL cols, 256 threads (8 warps), 2 CTAs/SM.
// Warp (w&3) -> row group 16*(w&3); (w>>2) -> column half.
// W is pre-packed per k-pair: float2(.x = hi half2, .y = lo half2).
// ---------------------------------------------------------------------------
template <int NCOL, bool POOL>
__global__ void __launch_bounds__(256, 2)
k_gemm16(const float* __restrict__ A, const float2* __restrict__ Wp,
         const float* __restrict__ sv, const float* __restrict__ dv,
         const float* __restrict__ bw, const float* __restrict__ bv,
         float* __restrict__ C) {
    constexpr int NT = NCOL / 16;       // 8-col tiles per warp (half of NCOL/8)
    constexpr int AS = 132;             // A smem stride (floats)
    constexpr int WS = NCOL + 4;        // W smem stride (float2 units)
    extern __shared__ char smraw[];
    float*  Asm = (float*)smraw;                               // [64][AS]
    float2* Wsm = (float2*)(smraw + 64 * AS * sizeof(float));  // [64][WS]

    const int tid = threadIdx.x;
    const int row0 = blockIdx.x * 64;

    // W pair tile: 64 x NCOL float2
    #pragma unroll 4
    for (int idx = tid; idx < 64 * NCOL; idx += 256) {
        int p = idx / NCOL, n = idx % NCOL;
        Wsm[p * WS + n] = Wp[idx];
    }
    // A tile (row-guarded, zero pad)
    {
        const float4* Ag = (const float4*)A;
        #pragma unroll
        for (int it = 0; it < 8; ++it) {
            int idx = it * 256 + tid;          // 0..2047
            int r = idx >> 5, kq = idx & 31;
            float4 v = make_float4(0.f, 0.f, 0.f, 0.f);
            if (row0 + r < NN) v = Ag[(size_t)(row0 + r) * 32 + kq];
            *(float4*)(Asm + r * AS + kq * 4) = v;
        }
    }
    __syncthreads();

    const int warp = tid >> 5, lane = tid & 31;
    const int gid = lane >> 2, tig = lane & 3;
    const int r0 = (warp & 3) * 16;
    const int cb = (warp >> 2) * (NCOL / 2);

    float c[NT][4];
    #pragma unroll
    for (int nt = 0; nt < NT; ++nt)
        #pragma unroll
        for (int q = 0; q < 4; ++q) c[nt][q] = 0.f;

    #pragma unroll
    for (int ks = 0; ks < 8; ++ks) {
        int k0 = ks * 16;
        // A fragments (m16n8k16): a0=(g, k0+2t..+1) a1=(g+8, same)
        //                         a2=(g, k0+2t+8..9) a3=(g+8, same)
        float2 aP0 = *(const float2*)(Asm + (r0 + gid) * AS + k0 + 2 * tig);
        float2 aP1 = *(const float2*)(Asm + (r0 + gid + 8) * AS + k0 + 2 * tig);
        float2 aP2 = *(const float2*)(Asm + (r0 + gid) * AS + k0 + 2 * tig + 8);
        float2 aP3 = *(const float2*)(Asm + (r0 + gid + 8) * AS + k0 + 2 * tig + 8);
        unsigned ah0, al0, ah1, al1, ah2, al2, ah3, al3;
        split2(aP0, ah0, al0);
        split2(aP1, ah1, al1);
        split2(aP2, ah2, al2);
        split2(aP3, ah3, al3);

        const float2* Wr0 = Wsm + (ks * 8 + tig) * WS + cb;       // b0 pair row
        const float2* Wr1 = Wsm + (ks * 8 + tig + 4) * WS + cb;   // b1 pair row
        #pragma unroll
        for (int nt = 0; nt < NT; ++nt) {
            float2 w0 = Wr0[nt * 8 + gid];
            float2 w1 = Wr1[nt * 8 + gid];
            unsigned bh0 = __float_as_uint(w0.x), bl0 = __float_as_uint(w0.y);
            unsigned bh1 = __float_as_uint(w1.x), bl1 = __float_as_uint(w1.y);
            mma_f16(c[nt], ah0, ah1, ah2, ah3, bh0, bh1);   // Ah*Wh
            mma_f16(c[nt], al0, al1, al2, al3, bh0, bh1);   // Al*Wh
            mma_f16(c[nt], ah0, ah1, ah2, ah3, bl0, bl1);   // Ah*Wl
        }
    }

    // Epilogue: c0/c1 -> row gid, cols 2tig/2tig+1; c2/c3 -> row gid+8.
    int rA = row0 + r0 + gid;
    int rB = rA + 8;
    float sA = 0.f, dA = 0.f, sB = 0.f, dB = 0.f;
    if (POOL) {
        if (rA < NN) { sA = sv[rA]; dA = dv[rA]; }
        if (rB < NN) { sB = sv[rB]; dB = dv[rB]; }
    }
    #pragma unroll
    for (int nt = 0; nt < NT; ++nt) {
        int col = cb + nt * 8 + 2 * tig;
        float v0 = bv[col], v1 = bv[col + 1];
        float w0 = 0.f, w1 = 0.f;
        if (POOL) { w0 = bw[col]; w1 = bw[col + 1]; }
        if (rA < NN) {
            float x0 = c[nt][0], x1 = c[nt][1];
            if (POOL) {
                x0 = fmaxf(x0 + sA * w0 + dA * v0, 0.f);
                x1 = fmaxf(x1 + sA * w1 + dA * v1, 0.f);
            } else { x0 += v0; x1 += v1; }
            *(float2*)&C[(size_t)rA * NCOL + col] = make_float2(x0, x1);
        }
        if (rB < NN) {
            float x0 = c[nt][2], x1 = c[nt][3];
            if (POOL) {
                x0 = fmaxf(x0 + sB * w0 + dB * v0, 0.f);
                x1 = fmaxf(x1 + sB * w1 + dB * v1, 0.f);
            } else { x0 += v0; x1 += v1; }
            *(float2*)&C[(size_t)rB * NCOL + col] = make_float2(x0, x1);
        }
    }
}

// ---------------------------------------------------------------------------
// Launch
// ---------------------------------------------------------------------------
extern "C" void kernel_launch(void* const* d_in, const int* in_sizes, int n_in,
                              void* d_out, int out_size) {
    const float* x    = (const float*)d_in[0];
    const void*  ei   = d_in[1];
    const float* W1   = (const float*)d_in[2];
    const float* b1   = (const float*)d_in[3];
    const float* W2   = (const float*)d_in[4];
    const float* b2   = (const float*)d_in[5];
    const float* Wout = (const float*)d_in[6];
    const float* bout = (const float*)d_in[7];
    float* out = (float*)d_out;

    void *pA, *pB, *pbW1, *pbW2, *pdeg, *psdeg, *pWp1, *pWp2, *pWpO;
    cudaGetSymbolAddress(&pA, g_bufA);
    cudaGetSymbolAddress(&pB, g_bufB);
    cudaGetSymbolAddress(&pbW1, g_bW1);
    cudaGetSymbolAddress(&pbW2, g_bW2);
    cudaGetSymbolAddress(&pdeg, g_deg);
    cudaGetSymbolAddress(&psdeg, g_sdeg);
    cudaGetSymbolAddress(&pWp1, g_Wp1);
    cudaGetSymbolAddress(&pWp2, g_Wp2);
    cudaGetSymbolAddress(&pWpO, g_WpO);
    float*  bufA = (float*)pA;
    float*  bufB = (float*)pB;
    float*  bW1  = (float*)pbW1;
    float*  bW2  = (float*)pbW2;
    float*  degv = (float*)pdeg;
    float*  sdeg = (float*)psdeg;
    float2* Wp1  = (float2*)pWp1;
    float2* Wp2  = (float2*)pWp2;
    float2* WpO  = (float2*)pWpO;

    const size_t SM128 = 64 * 132 * sizeof(float) + 64 * 132 * sizeof(float2); // ~101 KB
    const size_t SM64  = 64 * 132 * sizeof(float) + 64 * 68  * sizeof(float2); // ~68.6 KB
    cudaFuncSetAttribute(k_gemm16<128, true>,
                         cudaFuncAttributeMaxDynamicSharedMemorySize, (int)SM128);
    cudaFuncSetAttribute(k_gemm16<64, false>,
                         cudaFuncAttributeMaxDynamicSharedMemorySize, (int)SM64);

    const int GN  = (NN + 255) / 256;
    const int GE  = (EE + 255) / 256;
    const int GAG = (NN * 32 + 255) / 256;   // one warp per node
    const int GGM = (NN + 63) / 64;          // 64-row GEMM tiles

    // ---- CSR build + weight prep ----
    k_init<<<GN, 256>>>((const int*)ei);
    k_count<<<GE, 256>>>(ei);
    k_prep<<<82, 256>>>(W1, W2, Wout, b1, b2);
    k_bsum<<<NB, 256>>>();
    k_rowoff<<<NB, 256>>>();
    k_fill<<<GE, 256>>>(ei);
    k_sdeg<<<GN, 256>>>();

    // ---- Block 1: h1 = relu(A^2(x) @ W1^2 + s*(b1@W1) + d*b1) ----
    k_agg<<<GAG, 256>>>(x, bufA);
    k_agg<<<GAG, 256>>>(bufA, bufB);
    k_gemm16<128, true><<<GGM, 256, SM128>>>(bufB, Wp1, sdeg, degv, bW1, b1, bufA);

    // ---- Block 2: h2 = relu(A^2(h1) @ W2^2 + s*(b2@W2) + d*b2) ----
    k_agg<<<GAG, 256>>>(bufA, bufB);
    k_agg<<<GAG, 256>>>(bufB, bufA);
    k_gemm16<128, true><<<GGM, 256, SM128>>>(bufA, Wp2, sdeg, degv, bW2, b2, bufB);

    // ---- Output: out = h2 @ Wout + bout ----
    k_gemm16<64, false><<<GGM, 256, SM64>>>(bufB, WpO, nullptr, nullptr,
                                            nullptr, bout, out);
}

// round 11
// speedup vs baseline: 2.0111x; 1.0330x over previous
#include <cuda_runtime.h>
#include <cuda_fp16.h>
#include <cstdint>
#include <cstddef>
#include <cstring>

#define NN   50000
#define EE   600000
#define DD   128
#define OUTD 64
#define NB   ((NN + 255) / 256)   // 196 scan blocks

// ---------------------------------------------------------------------------
// Scratch state (no allocations allowed -> __device__ globals)
// ---------------------------------------------------------------------------
__device__ int   g_counts[NN];
__device__ int   g_cursor[NN];
__device__ int   g_rowoff[NN + 1];
__device__ int   g_csrsrc[EE];
__device__ float g_deg[NN];
__device__ float g_sdeg[NN];
__device__ float g_bufA[(size_t)NN * DD];        // fp32 GEMM inputs / h2
__device__ float g_bufB[(size_t)NN * DD];
__device__ uint2 g_x16[(size_t)NN * DD / 4];     // fp16 copy of x
__device__ uint2 g_h16A[(size_t)NN * DD / 4];    // fp16 intermediates
__device__ uint2 g_h16B[(size_t)NN * DD / 4];
__device__ float g_bW1[DD];
__device__ float g_bW2[DD];
// Weight tiles in k-pair split-fp16 layout: element (p, n) packs
//   .x = half2( hi(W[2p][n]), hi(W[2p+1][n]) ), .y = half2( lo residuals )
__device__ float2 g_Wp1[(DD / 2) * DD];    // split(W1@W1)
__device__ float2 g_Wp2[(DD / 2) * DD];    // split(W2@W2)
__device__ float2 g_WpO[(DD / 2) * OUTD];  // split(Wout)
__device__ int   g_is32;                   // sticky: set to 1 iff int32 detected

// ---------------------------------------------------------------------------
// helpers
// ---------------------------------------------------------------------------
__device__ __forceinline__ unsigned h2_bits(__half2 h) {
    unsigned u; memcpy(&u, &h, 4); return u;
}

__device__ __forceinline__ float2 pack_pair(float w0, float w1) {
    __half h0 = __float2half_rn(w0), h1 = __float2half_rn(w1);
    float r0 = w0 - __half2float(h0);
    float r1 = w1 - __half2float(h1);
    __half2 hi = __halves2half2(h0, h1);
    __half2 lo = __floats2half2_rn(r0, r1);
    float2 o;
    o.x = __uint_as_float(h2_bits(hi));
    o.y = __uint_as_float(h2_bits(lo));
    return o;
}

__device__ __forceinline__ void mma_f16(float c[4], unsigned a0, unsigned a1,
                                        unsigned a2, unsigned a3,
                                        unsigned b0, unsigned b1) {
    asm volatile(
        "mma.sync.aligned.m16n8k16.row.col.f32.f16.f16.f32 "
        "{%0,%1,%2,%3}, {%4,%5,%6,%7}, {%8,%9}, {%0,%1,%2,%3};"
        : "+f"(c[0]), "+f"(c[1]), "+f"(c[2]), "+f"(c[3])
        : "r"(a0), "r"(a1), "r"(a2), "r"(a3), "r"(b0), "r"(b1));
}

__device__ __forceinline__ void split2(float2 a, unsigned& hi, unsigned& lo) {
    __half2 h = __floats2half2_rn(a.x, a.y);
    float r0 = a.x - __low2float(h);
    float r1 = a.y - __high2float(h);
    __half2 l = __floats2half2_rn(r0, r1);
    hi = h2_bits(h);
    lo = h2_bits(l);
}

__device__ __forceinline__ void acc_add(float4& a, uint2 u) {
    __half2 p0, p1;
    memcpy(&p0, &u.x, 4); memcpy(&p1, &u.y, 4);
    float2 f0 = __half22float2(p0);
    float2 f1 = __half22float2(p1);
    a.x += f0.x; a.y += f0.y; a.z += f1.x; a.w += f1.y;
}

__device__ __forceinline__ int load_edge(const void* ei, int idx, int is32) {
    if (is32) return ((const int*)ei)[idx];
    return (int)((const long long*)ei)[idx];
}

// ---------------------------------------------------------------------------
// Mega-init (one launch): blocks [0,196): zero counts/cursor/sdeg + int-width
// detect; [196,278): weight prep; [278,3403): x -> fp16 convert.
// ---------------------------------------------------------------------------
__global__ void k_init(const int* __restrict__ eiw,
                       const float* __restrict__ W1, const float* __restrict__ W2,
                       const float* __restrict__ Wout,
                       const float* __restrict__ b1, const float* __restrict__ b2,
                       const float* __restrict__ x) {
    int blk = blockIdx.x;
    int tid = threadIdx.x;
    if (blk < 196) {
        int i = blk * 256 + tid;
        if (i < NN) { g_counts[i] = 0; g_cursor[i] = 0; g_sdeg[i] = 0.f; }
        // sticky detection: int64 little-endian has zero hi words; idempotent
        // across calls (write only 1, never reset -> no race, same result).
        if (i < 4096 && eiw[2 * i + 1] != 0) g_is32 = 1;
    } else if (blk < 278) {
        int b = blk - 196;
        if (b < 64) {
            const float* W = (b < 32) ? W1 : W2;
            float2* O = (b < 32) ? g_Wp1 : g_Wp2;
            int idx = (b & 31) * 256 + tid;
            int pp = idx >> 7, n = idx & 127;
            int r0 = 2 * pp, r1 = 2 * pp + 1;
            float s0 = 0.f, s1 = 0.f;
            #pragma unroll 8
            for (int k = 0; k < DD; ++k) {
                float wc = W[k * DD + n];
                s0 += W[r0 * DD + k] * wc;
                s1 += W[r1 * DD + k] * wc;
            }
            O[idx] = pack_pair(s0, s1);
        } else if (b < 80) {
            int idx = (b - 64) * 256 + tid;
            int pp = idx >> 6, n = idx & 63;
            float w0 = Wout[(2 * pp) * OUTD + n];
            float w1 = Wout[(2 * pp + 1) * OUTD + n];
            g_WpO[idx] = pack_pair(w0, w1);
        } else {
            const float* bb = (b == 80) ? b1 : b2;
            const float* W  = (b == 80) ? W1 : W2;
            float* bw = (b == 80) ? g_bW1 : g_bW2;
            if (tid < DD) {
                float s = 0.f;
                #pragma unroll 8
                for (int k = 0; k < DD; ++k) s += bb[k] * W[k * DD + tid];
                bw[tid] = s;
            }
        }
    } else {
        // x -> fp16: 2048 elems per block, 8 per thread (exact: 3125 blocks)
        size_t base = (size_t)(blk - 278) * 2048 + tid * 8;
        float4 v0 = *(const float4*)(x + base);
        float4 v1 = *(const float4*)(x + base + 4);
        __half2 h0 = __floats2half2_rn(v0.x, v0.y);
        __half2 h1 = __floats2half2_rn(v0.z, v0.w);
        __half2 h2 = __floats2half2_rn(v1.x, v1.y);
        __half2 h3 = __floats2half2_rn(v1.z, v1.w);
        uint4 o;
        o.x = h2_bits(h0); o.y = h2_bits(h1);
        o.z = h2_bits(h2); o.w = h2_bits(h3);
        *(uint4*)((char*)g_x16 + base * 2) = o;
    }
}

__global__ void k_count(const void* __restrict__ ei) {
    int e = blockIdx.x * blockDim.x + threadIdx.x;
    if (e >= EE) return;
    int is32 = g_is32;
    int dst = load_edge(ei, EE + e, is32);
    if ((unsigned)dst < (unsigned)NN)
        atomicAdd(&g_counts[dst], 1);
}

// Self-summing scan: each block reduces counts[0 .. blockIdx*256) for its
// prefix (L2-resident, independent loads), then local scan. No k_bsum launch.
__global__ void k_rowoff() {
    __shared__ int ws[8];
    __shared__ int s_prefix;
    int tid = threadIdx.x;
    int lane = tid & 31, wid = tid >> 5;

    int lim = blockIdx.x * 256;
    int pi = 0;
    for (int j = tid; j < lim; j += 256) pi += g_counts[j];
    #pragma unroll
    for (int o = 16; o > 0; o >>= 1) pi += __shfl_down_sync(0xffffffffu, pi, o);
    if (lane == 0) ws[wid] = pi;
    __syncthreads();
    if (tid == 0) {
        int s = 0;
        #pragma unroll
        for (int w = 0; w < 8; ++w) s += ws[w];
        s_prefix = s;
    }
    __syncthreads();
    int prefix = s_prefix;
    __syncthreads();

    int i = blockIdx.x * 256 + tid;
    int v = (i < NN) ? g_counts[i] : 0;
    int x = v;
    #pragma unroll
    for (int o = 1; o < 32; o <<= 1) {
        int t = __shfl_up_sync(0xffffffffu, x, o);
        if (lane >= o) x += t;
    }
    if (lane == 31) ws[wid] = x;
    __syncthreads();
    if (wid == 0) {
        int y = (lane < 8) ? ws[lane] : 0;
        #pragma unroll
        for (int o = 1; o < 8; o <<= 1) {
            int t = __shfl_up_sync(0xffffffffu, y, o);
            if (lane >= o) y += t;
        }
        if (lane < 8) ws[lane] = y;
    }
    __syncthreads();
    int excl = x - v + (wid ? ws[wid - 1] : 0) + prefix;
    if (i < NN) {
        g_rowoff[i] = excl;
        g_deg[i] = (float)v;
        if (i == NN - 1) g_rowoff[NN] = excl + v;
    }
}

// Fill CSR + accumulate sdeg = A(deg) via one float atomic per edge.
__global__ void k_fill(const void* __restrict__ ei) {
    int e = blockIdx.x * blockDim.x + threadIdx.x;
    if (e >= EE) return;
    int is32 = g_is32;
    int src = load_edge(ei, e, is32);
    int dst = load_edge(ei, EE + e, is32);
    if ((unsigned)dst >= (unsigned)NN) return;
    if ((unsigned)src >= (unsigned)NN) src = 0;
    int pos = g_rowoff[dst] + atomicAdd(&g_cursor[dst], 1);
    g_csrsrc[pos] = src;
    atomicAdd(&g_sdeg[dst], g_deg[src]);
}

// ---------------------------------------------------------------------------
// Aggregation over fp16 rows (256B). One warp/node; lane owns 4 cols (uint2).
// fp32 accumulate. Two variants: fp16 out (feeds another gather) / fp32 out
// (feeds a GEMM -> no extra rounding on the GEMM path).
// ---------------------------------------------------------------------------
__device__ __forceinline__ float4 gather_row(const uint2* __restrict__ in,
                                             int node, int lane) {
    float4 acc = make_float4(0.f, 0.f, 0.f, 0.f);
    int beg = g_rowoff[node], end = g_rowoff[node + 1];
    int e = beg;
    for (; e + 4 <= end; e += 4) {
        int s0 = g_csrsrc[e];
        int s1 = g_csrsrc[e + 1];
        int s2 = g_csrsrc[e + 2];
        int s3 = g_csrsrc[e + 3];
        uint2 u0 = in[(size_t)s0 * 32 + lane];
        uint2 u1 = in[(size_t)s1 * 32 + lane];
        uint2 u2 = in[(size_t)s2 * 32 + lane];
        uint2 u3 = in[(size_t)s3 * 32 + lane];
        acc_add(acc, u0); acc_add(acc, u1);
        acc_add(acc, u2); acc_add(acc, u3);
    }
    for (; e < end; ++e) {
        uint2 u0 = in[(size_t)g_csrsrc[e] * 32 + lane];
        acc_add(acc, u0);
    }
    return acc;
}

__global__ void __launch_bounds__(256) k_agg_hh(const uint2* __restrict__ in,
                                                uint2* __restrict__ out) {
    int w = (blockIdx.x * blockDim.x + threadIdx.x) >> 5;
    int lane = threadIdx.x & 31;
    if (w >= NN) return;
    float4 acc = gather_row(in, w, lane);
    __half2 h0 = __floats2half2_rn(acc.x, acc.y);
    __half2 h1 = __floats2half2_rn(acc.z, acc.w);
    uint2 o; o.x = h2_bits(h0); o.y = h2_bits(h1);
    out[(size_t)w * 32 + lane] = o;
}

__global__ void __launch_bounds__(256) k_agg_hf(const uint2* __restrict__ in,
                                                float* __restrict__ out) {
    int w = (blockIdx.x * blockDim.x + threadIdx.x) >> 5;
    int lane = threadIdx.x & 31;
    if (w >= NN) return;
    float4 acc = gather_row(in, w, lane);
    ((float4*)out)[(size_t)w * 32 + lane] = acc;
}

// ---------------------------------------------------------------------------
// fp16-3x tensor-core GEMM: C[N x NCOL] = A[N x 128] @ W[128 x NCOL]
//   POOL=true : C = relu(A@W + s_r*bw[c] + d_r*bv[c]); H16 -> fp16 output
//   POOL=false: C = A@W + bv[c]
// 64 rows x NCOL, 256 threads, 2 CTAs/SM. W pre-packed per k-pair (hi,lo).
// ---------------------------------------------------------------------------
template <int NCOL, bool POOL, bool H16>
__global__ void __launch_bounds__(256, 2)
k_gemm16(const float* __restrict__ A, const float2* __restrict__ Wp,
         const float* __restrict__ sv, const float* __restrict__ dv,
         const float* __restrict__ bw, const float* __restrict__ bv,
         void* __restrict__ Cv) {
    constexpr int NT = NCOL / 16;
    constexpr int AS = 132;
    constexpr int WS = NCOL + 4;
    extern __shared__ char smraw[];
    float*  Asm = (float*)smraw;
    float2* Wsm = (float2*)(smraw + 64 * AS * sizeof(float));

    const int tid = threadIdx.x;
    const int row0 = blockIdx.x * 64;

    #pragma unroll 4
    for (int idx = tid; idx < 64 * NCOL; idx += 256) {
        int p = idx / NCOL, n = idx % NCOL;
        Wsm[p * WS + n] = Wp[idx];
    }
    {
        const float4* Ag = (const float4*)A;
        #pragma unroll
        for (int it = 0; it < 8; ++it) {
            int idx = it * 256 + tid;
            int r = idx >> 5, kq = idx & 31;
            float4 v = make_float4(0.f, 0.f, 0.f, 0.f);
            if (row0 + r < NN) v = Ag[(size_t)(row0 + r) * 32 + kq];
            *(float4*)(Asm + r * AS + kq * 4) = v;
        }
    }
    __syncthreads();

    const int warp = tid >> 5, lane = tid & 31;
    const int gid = lane >> 2, tig = lane & 3;
    const int r0 = (warp & 3) * 16;
    const int cb = (warp >> 2) * (NCOL / 2);

    float c[NT][4];
    #pragma unroll
    for (int nt = 0; nt < NT; ++nt)
        #pragma unroll
        for (int q = 0; q < 4; ++q) c[nt][q] = 0.f;

    #pragma unroll
    for (int ks = 0; ks < 8; ++ks) {
        int k0 = ks * 16;
        float2 aP0 = *(const float2*)(Asm + (r0 + gid) * AS + k0 + 2 * tig);
        float2 aP1 = *(const float2*)(Asm + (r0 + gid + 8) * AS + k0 + 2 * tig);
        float2 aP2 = *(const float2*)(Asm + (r0 + gid) * AS + k0 + 2 * tig + 8);
        float2 aP3 = *(const float2*)(Asm + (r0 + gid + 8) * AS + k0 + 2 * tig + 8);
        unsigned ah0, al0, ah1, al1, ah2, al2, ah3, al3;
        split2(aP0, ah0, al0);
        split2(aP1, ah1, al1);
        split2(aP2, ah2, al2);
        split2(aP3, ah3, al3);

        const float2* Wr0 = Wsm + (ks * 8 + tig) * WS + cb;
        const float2* Wr1 = Wsm + (ks * 8 + tig + 4) * WS + cb;
        #pragma unroll
        for (int nt = 0; nt < NT; ++nt) {
            float2 w0 = Wr0[nt * 8 + gid];
            float2 w1 = Wr1[nt * 8 + gid];
            unsigned bh0 = __float_as_uint(w0.x), bl0 = __float_as_uint(w0.y);
            unsigned bh1 = __float_as_uint(w1.x), bl1 = __float_as_uint(w1.y);
            mma_f16(c[nt], ah0, ah1, ah2, ah3, bh0, bh1);   // Ah*Wh
            mma_f16(c[nt], al0, al1, al2, al3, bh0, bh1);   // Al*Wh
            mma_f16(c[nt], ah0, ah1, ah2, ah3, bl0, bl1);   // Ah*Wl
        }
    }

    int rA = row0 + r0 + gid;
    int rB = rA + 8;
    float sA = 0.f, dA = 0.f, sB = 0.f, dB = 0.f;
    if (POOL) {
        if (rA < NN) { sA = sv[rA]; dA = dv[rA]; }
        if (rB < NN) { sB = sv[rB]; dB = dv[rB]; }
    }
    #pragma unroll
    for (int nt = 0; nt < NT; ++nt) {
        int col = cb + nt * 8 + 2 * tig;
        float v0 = bv[col], v1 = bv[col + 1];
        float w0 = 0.f, w1 = 0.f;
        if (POOL) { w0 = bw[col]; w1 = bw[col + 1]; }
        float xa0 = c[nt][0], xa1 = c[nt][1];
        float xb0 = c[nt][2], xb1 = c[nt][3];
        if (POOL) {
            xa0 = fmaxf(xa0 + sA * w0 + dA * v0, 0.f);
            xa1 = fmaxf(xa1 + sA * w1 + dA * v1, 0.f);
            xb0 = fmaxf(xb0 + sB * w0 + dB * v0, 0.f);
            xb1 = fmaxf(xb1 + sB * w1 + dB * v1, 0.f);
        } else {
            xa0 += v0; xa1 += v1; xb0 += v0; xb1 += v1;
        }
        if (H16) {
            unsigned* C16 = (unsigned*)Cv;   // half2 as raw u32
            if (rA < NN)
                C16[(size_t)rA * (NCOL / 2) + (col >> 1)] =
                    h2_bits(__floats2half2_rn(xa0, xa1));
            if (rB < NN)
                C16[(size_t)rB * (NCOL / 2) + (col >> 1)] =
                    h2_bits(__floats2half2_rn(xb0, xb1));
        } else {
            float* C = (float*)Cv;
            if (rA < NN)
                *(float2*)&C[(size_t)rA * NCOL + col] = make_float2(xa0, xa1);
            if (rB < NN)
                *(float2*)&C[(size_t)rB * NCOL + col] = make_float2(xb0, xb1);
        }
    }
}

// ---------------------------------------------------------------------------
// Launch: 11 kernels total
// ---------------------------------------------------------------------------
extern "C" void kernel_launch(void* const* d_in, const int* in_sizes, int n_in,
                              void* d_out, int out_size) {
    const float* x    = (const float*)d_in[0];
    const void*  ei   = d_in[1];
    const float* W1   = (const float*)d_in[2];
    const float* b1   = (const float*)d_in[3];
    const float* W2   = (const float*)d_in[4];
    const float* b2   = (const float*)d_in[5];
    const float* Wout = (const float*)d_in[6];
    const float* bout = (const float*)d_in[7];
    float* out = (float*)d_out;

    void *pA, *pB, *pbW1, *pbW2, *pdeg, *psdeg, *pWp1, *pWp2, *pWpO;
    void *px16, *ph16A, *ph16B;
    cudaGetSymbolAddress(&pA, g_bufA);
    cudaGetSymbolAddress(&pB, g_bufB);
    cudaGetSymbolAddress(&pbW1, g_bW1);
    cudaGetSymbolAddress(&pbW2, g_bW2);
    cudaGetSymbolAddress(&pdeg, g_deg);
    cudaGetSymbolAddress(&psdeg, g_sdeg);
    cudaGetSymbolAddress(&pWp1, g_Wp1);
    cudaGetSymbolAddress(&pWp2, g_Wp2);
    cudaGetSymbolAddress(&pWpO, g_WpO);
    cudaGetSymbolAddress(&px16, g_x16);
    cudaGetSymbolAddress(&ph16A, g_h16A);
    cudaGetSymbolAddress(&ph16B, g_h16B);
    float*  bufA = (float*)pA;
    float*  bufB = (float*)pB;
    float*  bW1  = (float*)pbW1;
    float*  bW2  = (float*)pbW2;
    float*  degv = (float*)pdeg;
    float*  sdeg = (float*)psdeg;
    float2* Wp1  = (float2*)pWp1;
    float2* Wp2  = (float2*)pWp2;
    float2* WpO  = (float2*)pWpO;
    uint2*  x16  = (uint2*)px16;
    uint2*  h16A = (uint2*)ph16A;
    uint2*  h16B = (uint2*)ph16B;

    const size_t SM128 = 64 * 132 * sizeof(float) + 64 * 132 * sizeof(float2);
    const size_t SM64  = 64 * 132 * sizeof(float) + 64 * 68  * sizeof(float2);
    cudaFuncSetAttribute(k_gemm16<128, true, true>,
                         cudaFuncAttributeMaxDynamicSharedMemorySize, (int)SM128);
    cudaFuncSetAttribute(k_gemm16<128, true, false>,
                         cudaFuncAttributeMaxDynamicSharedMemorySize, (int)SM128);
    cudaFuncSetAttribute(k_gemm16<64, false, false>,
                         cudaFuncAttributeMaxDynamicSharedMemorySize, (int)SM64);

    const int GE    = (EE + 255) / 256;
    const int GAG   = (NN * 32 + 255) / 256;          // one warp per node
    const int GGM   = (NN + 63) / 64;                 // 64-row GEMM tiles
    const int GINIT = 278 + (NN * DD) / 2048;         // 3403

    // ---- setup: init+detect+prep+convert, CSR build ----
    k_init<<<GINIT, 256>>>((const int*)ei, W1, W2, Wout, b1, b2, x);
    k_count<<<GE, 256>>>(ei);
    k_rowoff<<<NB, 256>>>();
    k_fill<<<GE, 256>>>(ei);

    // ---- Block 1: h1 = relu(A^2(x) @ W1^2 + s*(b1@W1) + d*b1) ----
    k_agg_hh<<<GAG, 256>>>(x16, h16A);                        // y1 (fp16)
    k_agg_hf<<<GAG, 256>>>(h16A, bufA);                       // y2 (fp32)
    k_gemm16<128, true, true><<<GGM, 256, SM128>>>(bufA, Wp1, sdeg, degv,
                                                   bW1, b1, (void*)h16A); // h1

    // ---- Block 2: h2 = relu(A^2(h1) @ W2^2 + s*(b2@W2) + d*b2) ----
    k_agg_hh<<<GAG, 256>>>(h16A, h16B);                       // y3 (fp16)
    k_agg_hf<<<GAG, 256>>>(h16B, bufA);                       // y4 (fp32)
    k_gemm16<128, true, false><<<GGM, 256, SM128>>>(bufA, Wp2, sdeg, degv,
                                                    bW2, b2, (void*)bufB); // h2

    // ---- Output: out = h2 @ Wout + bout ----
    k_gemm16<64, false, false><<<GGM, 256, SM64>>>(bufB, WpO, nullptr, nullptr,
                                                   nullptr, bout, (void*)out);
}

// round 12
// speedup vs baseline: 2.0525x; 1.0206x over previous
#include <cuda_runtime.h>
#include <cuda_fp16.h>
#include <cstdint>
#include <cstddef>
#include <cstring>

#define NN   50000
#define EE   600000
#define DD   128
#define OUTD 64
#define NB   ((NN + 255) / 256)   // 196 scan blocks

// ---------------------------------------------------------------------------
// Scratch state (no allocations allowed -> __device__ globals)
// ---------------------------------------------------------------------------
__device__ int   g_counts[NN];
__device__ int   g_cursor[NN];
__device__ int   g_rowoff[NN + 1];
__device__ int   g_csrsrc[EE];
__device__ float g_deg[NN];
__device__ float g_sdeg[NN];
__device__ float g_bufA[(size_t)NN * DD];        // fp32 GEMM inputs
__device__ uint2 g_x16[(size_t)NN * DD / 4];     // fp16 copy of x
__device__ uint2 g_h16A[(size_t)NN * DD / 4];    // fp16 intermediates
__device__ uint2 g_h16B[(size_t)NN * DD / 4];
__device__ float g_bW1[DD];
__device__ float g_bW2[DD];
// Weight tiles in k-pair split-fp16 layout: element (p, n) packs
//   .x = half2( hi(W[2p][n]), hi(W[2p+1][n]) ), .y = half2( lo residuals )
__device__ float2 g_Wp1[(DD / 2) * DD];    // split(W1@W1)
__device__ float2 g_Wp2[(DD / 2) * DD];    // split(W2@W2)
__device__ float2 g_WpO[(DD / 2) * OUTD];  // split(Wout)
__device__ int   g_is32;                   // sticky: 1 iff int32 detected

// ---------------------------------------------------------------------------
// helpers
// ---------------------------------------------------------------------------
__device__ __forceinline__ unsigned h2_bits(__half2 h) {
    unsigned u; memcpy(&u, &h, 4); return u;
}

__device__ __forceinline__ float2 pack_pair(float w0, float w1) {
    __half h0 = __float2half_rn(w0), h1 = __float2half_rn(w1);
    float r0 = w0 - __half2float(h0);
    float r1 = w1 - __half2float(h1);
    __half2 hi = __halves2half2(h0, h1);
    __half2 lo = __floats2half2_rn(r0, r1);
    float2 o;
    o.x = __uint_as_float(h2_bits(hi));
    o.y = __uint_as_float(h2_bits(lo));
    return o;
}

__device__ __forceinline__ void mma_f16(float c[4], unsigned a0, unsigned a1,
                                        unsigned a2, unsigned a3,
                                        unsigned b0, unsigned b1) {
    asm volatile(
        "mma.sync.aligned.m16n8k16.row.col.f32.f16.f16.f32 "
        "{%0,%1,%2,%3}, {%4,%5,%6,%7}, {%8,%9}, {%0,%1,%2,%3};"
        : "+f"(c[0]), "+f"(c[1]), "+f"(c[2]), "+f"(c[3])
        : "r"(a0), "r"(a1), "r"(a2), "r"(a3), "r"(b0), "r"(b1));
}

__device__ __forceinline__ void split2(float2 a, unsigned& hi, unsigned& lo) {
    __half2 h = __floats2half2_rn(a.x, a.y);
    float r0 = a.x - __low2float(h);
    float r1 = a.y - __high2float(h);
    __half2 l = __floats2half2_rn(r0, r1);
    hi = h2_bits(h);
    lo = h2_bits(l);
}

__device__ __forceinline__ void acc_add(float4& a, uint2 u) {
    __half2 p0, p1;
    memcpy(&p0, &u.x, 4); memcpy(&p1, &u.y, 4);
    float2 f0 = __half22float2(p0);
    float2 f1 = __half22float2(p1);
    a.x += f0.x; a.y += f0.y; a.z += f1.x; a.w += f1.y;
}

__device__ __forceinline__ int load_edge(const void* ei, int idx, int is32) {
    if (is32) return ((const int*)ei)[idx];
    return (int)((const long long*)ei)[idx];
}

// 3x-split fp16 mainloop over fp32 A-smem tile (stride 132) and a packed
// split-W smem tile (float2, stride WS). Warp covers rows [r0,r0+16),
// columns [cb, cb + NT*8) relative to the Wsm tile base column cb.
template <int NT, int WS>
__device__ __forceinline__ void tc_loop(const float* Asm, const float2* Wsm,
                                        int r0, int cb, int gid, int tig,
                                        float (*c)[4]) {
    #pragma unroll
    for (int ks = 0; ks < 8; ++ks) {
        int k0 = ks * 16;
        float2 aP0 = *(const float2*)(Asm + (r0 + gid) * 132 + k0 + 2 * tig);
        float2 aP1 = *(const float2*)(Asm + (r0 + gid + 8) * 132 + k0 + 2 * tig);
        float2 aP2 = *(const float2*)(Asm + (r0 + gid) * 132 + k0 + 2 * tig + 8);
        float2 aP3 = *(const float2*)(Asm + (r0 + gid + 8) * 132 + k0 + 2 * tig + 8);
        unsigned ah0, al0, ah1, al1, ah2, al2, ah3, al3;
        split2(aP0, ah0, al0);
        split2(aP1, ah1, al1);
        split2(aP2, ah2, al2);
        split2(aP3, ah3, al3);
        const float2* Wr0 = Wsm + (ks * 8 + tig) * WS + cb;
        const float2* Wr1 = Wsm + (ks * 8 + tig + 4) * WS + cb;
        #pragma unroll
        for (int nt = 0; nt < NT; ++nt) {
            float2 w0 = Wr0[nt * 8 + gid];
            float2 w1 = Wr1[nt * 8 + gid];
            unsigned bh0 = __float_as_uint(w0.x), bl0 = __float_as_uint(w0.y);
            unsigned bh1 = __float_as_uint(w1.x), bl1 = __float_as_uint(w1.y);
            mma_f16(c[nt], ah0, ah1, ah2, ah3, bh0, bh1);   // Ah*Wh
            mma_f16(c[nt], al0, al1, al2, al3, bh0, bh1);   // Al*Wh
            mma_f16(c[nt], ah0, ah1, ah2, ah3, bl0, bl1);   // Ah*Wl
        }
    }
}

// ---------------------------------------------------------------------------
// Mega-init (one launch): blocks [0,196): zero counts/cursor + int-width
// detect; [196,278): weight prep; [278,3403): x -> fp16 convert.
// ---------------------------------------------------------------------------
__global__ void k_init(const int* __restrict__ eiw,
                       const float* __restrict__ W1, const float* __restrict__ W2,
                       const float* __restrict__ Wout,
                       const float* __restrict__ b1, const float* __restrict__ b2,
                       const float* __restrict__ x) {
    int blk = blockIdx.x;
    int tid = threadIdx.x;
    if (blk < 196) {
        int i = blk * 256 + tid;
        if (i < NN) { g_counts[i] = 0; g_cursor[i] = 0; }
        // sticky detection: int64 little-endian has zero hi words; idempotent
        if (i < 4096 && eiw[2 * i + 1] != 0) g_is32 = 1;
    } else if (blk < 278) {
        int b = blk - 196;
        if (b < 64) {
            const float* W = (b < 32) ? W1 : W2;
            float2* O = (b < 32) ? g_Wp1 : g_Wp2;
            int idx = (b & 31) * 256 + tid;
            int pp = idx >> 7, n = idx & 127;
            int r0 = 2 * pp, r1 = 2 * pp + 1;
            float s0 = 0.f, s1 = 0.f;
            #pragma unroll 8
            for (int k = 0; k < DD; ++k) {
                float wc = W[k * DD + n];
                s0 += W[r0 * DD + k] * wc;
                s1 += W[r1 * DD + k] * wc;
            }
            O[idx] = pack_pair(s0, s1);
        } else if (b < 80) {
            int idx = (b - 64) * 256 + tid;
            int pp = idx >> 6, n = idx & 63;
            float w0 = Wout[(2 * pp) * OUTD + n];
            float w1 = Wout[(2 * pp + 1) * OUTD + n];
            g_WpO[idx] = pack_pair(w0, w1);
        } else {
            const float* bb = (b == 80) ? b1 : b2;
            const float* W  = (b == 80) ? W1 : W2;
            float* bw = (b == 80) ? g_bW1 : g_bW2;
            if (tid < DD) {
                float s = 0.f;
                #pragma unroll 8
                for (int k = 0; k < DD; ++k) s += bb[k] * W[k * DD + tid];
                bw[tid] = s;
            }
        }
    } else {
        size_t base = (size_t)(blk - 278) * 2048 + tid * 8;
        float4 v0 = *(const float4*)(x + base);
        float4 v1 = *(const float4*)(x + base + 4);
        __half2 h0 = __floats2half2_rn(v0.x, v0.y);
        __half2 h1 = __floats2half2_rn(v0.z, v0.w);
        __half2 h2 = __floats2half2_rn(v1.x, v1.y);
        __half2 h3 = __floats2half2_rn(v1.z, v1.w);
        uint4 o;
        o.x = h2_bits(h0); o.y = h2_bits(h1);
        o.z = h2_bits(h2); o.w = h2_bits(h3);
        *(uint4*)((char*)g_x16 + base * 2) = o;
    }
}

__global__ void k_count(const void* __restrict__ ei) {
    int e = blockIdx.x * blockDim.x + threadIdx.x;
    if (e >= EE) return;
    int is32 = g_is32;
    int dst = load_edge(ei, EE + e, is32);
    if ((unsigned)dst < (unsigned)NN)
        atomicAdd(&g_counts[dst], 1);
}

// Self-summing scan: each block reduces counts[0 .. blockIdx*256) for its
// prefix (L2-resident), then local scan.
__global__ void k_rowoff() {
    __shared__ int ws[8];
    __shared__ int s_prefix;
    int tid = threadIdx.x;
    int lane = tid & 31, wid = tid >> 5;

    int lim = blockIdx.x * 256;
    int pi = 0;
    for (int j = tid; j < lim; j += 256) pi += g_counts[j];
    #pragma unroll
    for (int o = 16; o > 0; o >>= 1) pi += __shfl_down_sync(0xffffffffu, pi, o);
    if (lane == 0) ws[wid] = pi;
    __syncthreads();
    if (tid == 0) {
        int s = 0;
        #pragma unroll
        for (int w = 0; w < 8; ++w) s += ws[w];
        s_prefix = s;
    }
    __syncthreads();
    int prefix = s_prefix;
    __syncthreads();

    int i = blockIdx.x * 256 + tid;
    int v = (i < NN) ? g_counts[i] : 0;
    int x = v;
    #pragma unroll
    for (int o = 1; o < 32; o <<= 1) {
        int t = __shfl_up_sync(0xffffffffu, x, o);
        if (lane >= o) x += t;
    }
    if (lane == 31) ws[wid] = x;
    __syncthreads();
    if (wid == 0) {
        int y = (lane < 8) ? ws[lane] : 0;
        #pragma unroll
        for (int o = 1; o < 8; o <<= 1) {
            int t = __shfl_up_sync(0xffffffffu, y, o);
            if (lane >= o) y += t;
        }
        if (lane < 8) ws[lane] = y;
    }
    __syncthreads();
    int excl = x - v + (wid ? ws[wid - 1] : 0) + prefix;
    if (i < NN) {
        g_rowoff[i] = excl;
        g_deg[i] = (float)v;
        if (i == NN - 1) g_rowoff[NN] = excl + v;
    }
}

// Fill CSR. Single cursor atomic per edge (sdeg moved to agg pass 1).
__global__ void k_fill(const void* __restrict__ ei) {
    int e = blockIdx.x * blockDim.x + threadIdx.x;
    if (e >= EE) return;
    int is32 = g_is32;
    int src = load_edge(ei, e, is32);
    int dst = load_edge(ei, EE + e, is32);
    if ((unsigned)dst >= (unsigned)NN) return;
    if ((unsigned)src >= (unsigned)NN) src = 0;
    int pos = g_rowoff[dst] + atomicAdd(&g_cursor[dst], 1);
    g_csrsrc[pos] = src;
}

// ---------------------------------------------------------------------------
// Aggregation over fp16 rows. One warp/node; lane owns 4 cols (uint2).
// SDEG: also accumulate sdeg[node] = sum deg[src] (pass 1 only).
// ---------------------------------------------------------------------------
template <bool SDEG>
__device__ __forceinline__ float4 gather_row(const uint2* __restrict__ in,
                                             int node, int lane, float& sd) {
    float4 acc = make_float4(0.f, 0.f, 0.f, 0.f);
    int beg = g_rowoff[node], end = g_rowoff[node + 1];
    int e = beg;
    for (; e + 4 <= end; e += 4) {
        int s0 = g_csrsrc[e];
        int s1 = g_csrsrc[e + 1];
        int s2 = g_csrsrc[e + 2];
        int s3 = g_csrsrc[e + 3];
        uint2 u0 = in[(size_t)s0 * 32 + lane];
        uint2 u1 = in[(size_t)s1 * 32 + lane];
        uint2 u2 = in[(size_t)s2 * 32 + lane];
        uint2 u3 = in[(size_t)s3 * 32 + lane];
        if (SDEG) sd += (g_deg[s0] + g_deg[s1]) + (g_deg[s2] + g_deg[s3]);
        acc_add(acc, u0); acc_add(acc, u1);
        acc_add(acc, u2); acc_add(acc, u3);
    }
    for (; e < end; ++e) {
        int s0 = g_csrsrc[e];
        uint2 u0 = in[(size_t)s0 * 32 + lane];
        if (SDEG) sd += g_deg[s0];
        acc_add(acc, u0);
    }
    return acc;
}

template <bool SDEG>
__global__ void __launch_bounds__(256) k_agg_hh(const uint2* __restrict__ in,
                                                uint2* __restrict__ out) {
    int w = (blockIdx.x * blockDim.x + threadIdx.x) >> 5;
    int lane = threadIdx.x & 31;
    if (w >= NN) return;
    float sd = 0.f;
    float4 acc = gather_row<SDEG>(in, w, lane, sd);
    __half2 h0 = __floats2half2_rn(acc.x, acc.y);
    __half2 h1 = __floats2half2_rn(acc.z, acc.w);
    uint2 o; o.x = h2_bits(h0); o.y = h2_bits(h1);
    out[(size_t)w * 32 + lane] = o;
    if (SDEG && lane == 0) g_sdeg[w] = sd;
}

__global__ void __launch_bounds__(256) k_agg_hf(const uint2* __restrict__ in,
                                                float* __restrict__ out) {
    int w = (blockIdx.x * blockDim.x + threadIdx.x) >> 5;
    int lane = threadIdx.x & 31;
    if (w >= NN) return;
    float sd = 0.f;
    float4 acc = gather_row<false>(in, w, lane, sd);
    ((float4*)out)[(size_t)w * 32 + lane] = acc;
}

// ---------------------------------------------------------------------------
// Pool GEMM 1: h1 = relu(A@W + s*bw + d*bv), fp16 output (feeds gather).
// 64 rows x 128 cols, 256 threads, 2 CTAs/SM.
// ---------------------------------------------------------------------------
__global__ void __launch_bounds__(256, 2)
k_gemm_pool(const float* __restrict__ A, const float2* __restrict__ Wp,
            const float* __restrict__ sv, const float* __restrict__ dv,
            const float* __restrict__ bw, const float* __restrict__ bv,
            unsigned* __restrict__ C16) {
    constexpr int WS = 132;
    extern __shared__ char smraw[];
    float*  Asm = (float*)smraw;
    float2* Wsm = (float2*)(smraw + 64 * 132 * sizeof(float));

    const int tid = threadIdx.x;
    const int row0 = blockIdx.x * 64;

    #pragma unroll 4
    for (int idx = tid; idx < 64 * 128; idx += 256) {
        int p = idx >> 7, n = idx & 127;
        Wsm[p * WS + n] = Wp[idx];
    }
    {
        const float4* Ag = (const float4*)A;
        #pragma unroll
        for (int it = 0; it < 8; ++it) {
            int idx = it * 256 + tid;
            int r = idx >> 5, kq = idx & 31;
            float4 v = make_float4(0.f, 0.f, 0.f, 0.f);
            if (row0 + r < NN) v = Ag[(size_t)(row0 + r) * 32 + kq];
            *(float4*)(Asm + r * 132 + kq * 4) = v;
        }
    }
    __syncthreads();

    const int warp = tid >> 5, lane = tid & 31;
    const int gid = lane >> 2, tig = lane & 3;
    const int r0 = (warp & 3) * 16;
    const int cb = (warp >> 2) * 64;

    float c[8][4];
    #pragma unroll
    for (int nt = 0; nt < 8; ++nt)
        #pragma unroll
        for (int q = 0; q < 4; ++q) c[nt][q] = 0.f;

    tc_loop<8, WS>(Asm, Wsm, r0, cb, gid, tig, c);

    int rA = row0 + r0 + gid;
    int rB = rA + 8;
    float sA = 0.f, dA = 0.f, sB = 0.f, dB = 0.f;
    if (rA < NN) { sA = sv[rA]; dA = dv[rA]; }
    if (rB < NN) { sB = sv[rB]; dB = dv[rB]; }
    #pragma unroll
    for (int nt = 0; nt < 8; ++nt) {
        int col = cb + nt * 8 + 2 * tig;
        float v0 = bv[col], v1 = bv[col + 1];
        float w0 = bw[col], w1 = bw[col + 1];
        if (rA < NN) {
            float x0 = fmaxf(c[nt][0] + sA * w0 + dA * v0, 0.f);
            float x1 = fmaxf(c[nt][1] + sA * w1 + dA * v1, 0.f);
            C16[(size_t)rA * 64 + (col >> 1)] = h2_bits(__floats2half2_rn(x0, x1));
        }
        if (rB < NN) {
            float x0 = fmaxf(c[nt][2] + sB * w0 + dB * v0, 0.f);
            float x1 = fmaxf(c[nt][3] + sB * w1 + dB * v1, 0.f);
            C16[(size_t)rB * 64 + (col >> 1)] = h2_bits(__floats2half2_rn(x0, x1));
        }
    }
}

// ---------------------------------------------------------------------------
// Fused pool GEMM 2 + output GEMM:
//   h = relu(A@Wsq2 + s*bw + d*bv)   (written back into A smem tile)
//   out = h @ Wout + bout
// Smem peak unchanged (101 KB) -> still 2 CTAs/SM. Saves the h2 round-trip.
// ---------------------------------------------------------------------------
__global__ void __launch_bounds__(256, 2)
k_gemm2out(const float* __restrict__ A, const float2* __restrict__ Wp2,
           const float2* __restrict__ WpO,
           const float* __restrict__ sv, const float* __restrict__ dv,
           const float* __restrict__ bw, const float* __restrict__ bv,
           const float* __restrict__ bvo, float* __restrict__ out) {
    constexpr int WS = 132, WS2 = 68;
    extern __shared__ char smraw[];
    float*  Asm = (float*)smraw;
    float2* Wsm = (float2*)(smraw + 64 * 132 * sizeof(float));

    const int tid = threadIdx.x;
    const int row0 = blockIdx.x * 64;

    #pragma unroll 4
    for (int idx = tid; idx < 64 * 128; idx += 256) {
        int p = idx >> 7, n = idx & 127;
        Wsm[p * WS + n] = Wp2[idx];
    }
    {
        const float4* Ag = (const float4*)A;
        #pragma unroll
        for (int it = 0; it < 8; ++it) {
            int idx = it * 256 + tid;
            int r = idx >> 5, kq = idx & 31;
            float4 v = make_float4(0.f, 0.f, 0.f, 0.f);
            if (row0 + r < NN) v = Ag[(size_t)(row0 + r) * 32 + kq];
            *(float4*)(Asm + r * 132 + kq * 4) = v;
        }
    }
    __syncthreads();

    const int warp = tid >> 5, lane = tid & 31;
    const int gid = lane >> 2, tig = lane & 3;
    const int r0 = (warp & 3) * 16;
    const int cb = (warp >> 2) * 64;

    float c[8][4];
    #pragma unroll
    for (int nt = 0; nt < 8; ++nt)
        #pragma unroll
        for (int q = 0; q < 4; ++q) c[nt][q] = 0.f;

    tc_loop<8, WS>(Asm, Wsm, r0, cb, gid, tig, c);

    __syncthreads();   // all warps done reading Asm / Wsm

    // relu(h) -> Asm (rows >= NN keep stale data; their stores are guarded)
    {
        int rA = row0 + r0 + gid;
        int rB = rA + 8;
        float sA = 0.f, dA = 0.f, sB = 0.f, dB = 0.f;
        if (rA < NN) { sA = sv[rA]; dA = dv[rA]; }
        if (rB < NN) { sB = sv[rB]; dB = dv[rB]; }
        #pragma unroll
        for (int nt = 0; nt < 8; ++nt) {
            int col = cb + nt * 8 + 2 * tig;
            float v0 = bv[col], v1 = bv[col + 1];
            float w0 = bw[col], w1 = bw[col + 1];
            float xa0 = fmaxf(c[nt][0] + sA * w0 + dA * v0, 0.f);
            float xa1 = fmaxf(c[nt][1] + sA * w1 + dA * v1, 0.f);
            float xb0 = fmaxf(c[nt][2] + sB * w0 + dB * v0, 0.f);
            float xb1 = fmaxf(c[nt][3] + sB * w1 + dB * v1, 0.f);
            *(float2*)(Asm + (r0 + gid) * 132 + col)     = make_float2(xa0, xa1);
            *(float2*)(Asm + (r0 + gid + 8) * 132 + col) = make_float2(xb0, xb1);
        }
    }
    // Wout split tile over the dead Wsq2 region
    #pragma unroll 4
    for (int idx = tid; idx < 64 * OUTD; idx += 256) {
        int p = idx >> 6, n = idx & 63;
        Wsm[p * WS2 + n] = WpO[idx];
    }
    __syncthreads();

    const int cb2 = (warp >> 2) * 32;
    float c2[4][4];
    #pragma unroll
    for (int nt = 0; nt < 4; ++nt)
        #pragma unroll
        for (int q = 0; q < 4; ++q) c2[nt][q] = 0.f;

    tc_loop<4, WS2>(Asm, Wsm, r0, cb2, gid, tig, c2);

    int rA = row0 + r0 + gid;
    int rB = rA + 8;
    #pragma unroll
    for (int nt = 0; nt < 4; ++nt) {
        int col = cb2 + nt * 8 + 2 * tig;
        float v0 = bvo[col], v1 = bvo[col + 1];
        if (rA < NN)
            *(float2*)&out[(size_t)rA * OUTD + col] =
                make_float2(c2[nt][0] + v0, c2[nt][1] + v1);
        if (rB < NN)
            *(float2*)&out[(size_t)rB * OUTD + col] =
                make_float2(c2[nt][2] + v0, c2[nt][3] + v1);
    }
}

// ---------------------------------------------------------------------------
// Launch: 10 kernels total
// ---------------------------------------------------------------------------
extern "C" void kernel_launch(void* const* d_in, const int* in_sizes, int n_in,
                              void* d_out, int out_size) {
    const float* x    = (const float*)d_in[0];
    const void*  ei   = d_in[1];
    const float* W1   = (const float*)d_in[2];
    const float* b1   = (const float*)d_in[3];
    const float* W2   = (const float*)d_in[4];
    const float* b2   = (const float*)d_in[5];
    const float* Wout = (const float*)d_in[6];
    const float* bout = (const float*)d_in[7];
    float* out = (float*)d_out;

    void *pA, *pbW1, *pbW2, *pdeg, *psdeg, *pWp1, *pWp2, *pWpO;
    void *px16, *ph16A, *ph16B;
    cudaGetSymbolAddress(&pA, g_bufA);
    cudaGetSymbolAddress(&pbW1, g_bW1);
    cudaGetSymbolAddress(&pbW2, g_bW2);
    cudaGetSymbolAddress(&pdeg, g_deg);
    cudaGetSymbolAddress(&psdeg, g_sdeg);
    cudaGetSymbolAddress(&pWp1, g_Wp1);
    cudaGetSymbolAddress(&pWp2, g_Wp2);
    cudaGetSymbolAddress(&pWpO, g_WpO);
    cudaGetSymbolAddress(&px16, g_x16);
    cudaGetSymbolAddress(&ph16A, g_h16A);
    cudaGetSymbolAddress(&ph16B, g_h16B);
    float*  bufA = (float*)pA;
    float*  bW1  = (float*)pbW1;
    float*  bW2  = (float*)pbW2;
    float*  degv = (float*)pdeg;
    float*  sdeg = (float*)psdeg;
    float2* Wp1  = (float2*)pWp1;
    float2* Wp2  = (float2*)pWp2;
    float2* WpO  = (float2*)pWpO;
    uint2*  x16  = (uint2*)px16;
    uint2*  h16A = (uint2*)ph16A;
    uint2*  h16B = (uint2*)ph16B;

    const size_t SMF = 64 * 132 * sizeof(float) + 64 * 132 * sizeof(float2); // ~101 KB
    cudaFuncSetAttribute(k_gemm_pool,
                         cudaFuncAttributeMaxDynamicSharedMemorySize, (int)SMF);
    cudaFuncSetAttribute(k_gemm2out,
                         cudaFuncAttributeMaxDynamicSharedMemorySize, (int)SMF);

    const int GE    = (EE + 255) / 256;
    const int GAG   = (NN * 32 + 255) / 256;          // one warp per node
    const int GGM   = (NN + 63) / 64;                 // 64-row GEMM tiles
    const int GINIT = 278 + (NN * DD) / 2048;         // 3403

    // ---- setup: init+detect+prep+convert, CSR build ----
    k_init<<<GINIT, 256>>>((const int*)ei, W1, W2, Wout, b1, b2, x);
    k_count<<<GE, 256>>>(ei);
    k_rowoff<<<NB, 256>>>();
    k_fill<<<GE, 256>>>(ei);

    // ---- Block 1: h1 = relu(A^2(x) @ W1^2 + s*(b1@W1) + d*b1) ----
    k_agg_hh<true><<<GAG, 256>>>(x16, h16A);                  // y1 + sdeg
    k_agg_hf<<<GAG, 256>>>(h16A, bufA);                       // y2 (fp32)
    k_gemm_pool<<<GGM, 256, SMF>>>(bufA, Wp1, sdeg, degv, bW1, b1,
                                   (unsigned*)h16A);          // h1 (fp16)

    // ---- Block 2 + output (fused) ----
    k_agg_hh<false><<<GAG, 256>>>(h16A, h16B);                // y3 (fp16)
    k_agg_hf<<<GAG, 256>>>(h16B, bufA);                       // y4 (fp32)
    k_gemm2out<<<GGM, 256, SMF>>>(bufA, Wp2, WpO, sdeg, degv, bW2, b2,
                                  bout, out);
}

// round 13
// speedup vs baseline: 2.2593x; 1.1007x over previous
#include <cuda_runtime.h>
#include <cuda_fp16.h>
#include <cstdint>
#include <cstddef>
#include <cstring>

#define NN   50000
#define EE   600000
#define DD   128
#define OUTD 64
#define NB   ((NN + 255) / 256)   // 196 scan blocks

// ---------------------------------------------------------------------------
// Scratch state (no allocations allowed -> __device__ globals)
// ---------------------------------------------------------------------------
__device__ int   g_counts[NN];
__device__ int   g_rowoff[NN + 1];
__device__ int   g_ordinal[EE];
__device__ int   g_csrsrc[EE];
__device__ float g_deg[NN];
__device__ float g_sdeg[NN];
__device__ uint2 g_f16a[(size_t)NN * DD / 4];   // z1 / z2
__device__ uint2 g_f16b[(size_t)NN * DD / 4];   // t  / u
__device__ uint2 g_f16c[(size_t)NN * DD / 4];   // h1 / h2
__device__ float g_bW1[DD];
__device__ float g_bW2[DD];
// Weight tiles in k-pair split-fp16 layout: element (p, n) packs
//   .x = half2( hi(W[2p][n]), hi(W[2p+1][n]) ), .y = half2( lo residuals )
__device__ float2 g_Wp1[(DD / 2) * DD];    // split(W1@W1)
__device__ float2 g_Wp2[(DD / 2) * DD];    // split(W2@W2)
__device__ float2 g_WpO[(DD / 2) * OUTD];  // split(Wout)
__device__ int   g_is32;                   // sticky: 1 iff int32 detected

// ---------------------------------------------------------------------------
// helpers
// ---------------------------------------------------------------------------
__device__ __forceinline__ unsigned h2_bits(__half2 h) {
    unsigned u; memcpy(&u, &h, 4); return u;
}

__device__ __forceinline__ float2 pack_pair(float w0, float w1) {
    __half h0 = __float2half_rn(w0), h1 = __float2half_rn(w1);
    float r0 = w0 - __half2float(h0);
    float r1 = w1 - __half2float(h1);
    __half2 hi = __halves2half2(h0, h1);
    __half2 lo = __floats2half2_rn(r0, r1);
    float2 o;
    o.x = __uint_as_float(h2_bits(hi));
    o.y = __uint_as_float(h2_bits(lo));
    return o;
}

__device__ __forceinline__ void mma_f16(float c[4], unsigned a0, unsigned a1,
                                        unsigned a2, unsigned a3,
                                        unsigned b0, unsigned b1) {
    asm volatile(
        "mma.sync.aligned.m16n8k16.row.col.f32.f16.f16.f32 "
        "{%0,%1,%2,%3}, {%4,%5,%6,%7}, {%8,%9}, {%0,%1,%2,%3};"
        : "+f"(c[0]), "+f"(c[1]), "+f"(c[2]), "+f"(c[3])
        : "r"(a0), "r"(a1), "r"(a2), "r"(a3), "r"(b0), "r"(b1));
}

__device__ __forceinline__ void split2(float2 a, unsigned& hi, unsigned& lo) {
    __half2 h = __floats2half2_rn(a.x, a.y);
    float r0 = a.x - __low2float(h);
    float r1 = a.y - __high2float(h);
    __half2 l = __floats2half2_rn(r0, r1);
    hi = h2_bits(h);
    lo = h2_bits(l);
}

__device__ __forceinline__ void acc_add(float4& a, uint2 u) {
    __half2 p0, p1;
    memcpy(&p0, &u.x, 4); memcpy(&p1, &u.y, 4);
    float2 f0 = __half22float2(p0);
    float2 f1 = __half22float2(p1);
    a.x += f0.x; a.y += f0.y; a.z += f1.x; a.w += f1.y;
}

__device__ __forceinline__ int load_edge(const void* ei, int idx, int is32) {
    if (is32) return ((const int*)ei)[idx];
    return (int)((const long long*)ei)[idx];
}

// 3x-split fp16 mainloop, fp32 A-smem tile (stride 132), split-W tile (stride
// WS float2). Warp: rows [r0,r0+16), cols [cb*2, cb*2+NT*8) of the W tile.
template <int NT, int WS>
__device__ __forceinline__ void tc_loop(const float* Asm, const float2* Wsm,
                                        int r0, int cb, int gid, int tig,
                                        float (*c)[4]) {
    #pragma unroll
    for (int ks = 0; ks < 8; ++ks) {
        int k0 = ks * 16;
        float2 aP0 = *(const float2*)(Asm + (r0 + gid) * 132 + k0 + 2 * tig);
        float2 aP1 = *(const float2*)(Asm + (r0 + gid + 8) * 132 + k0 + 2 * tig);
        float2 aP2 = *(const float2*)(Asm + (r0 + gid) * 132 + k0 + 2 * tig + 8);
        float2 aP3 = *(const float2*)(Asm + (r0 + gid + 8) * 132 + k0 + 2 * tig + 8);
        unsigned ah0, al0, ah1, al1, ah2, al2, ah3, al3;
        split2(aP0, ah0, al0);
        split2(aP1, ah1, al1);
        split2(aP2, ah2, al2);
        split2(aP3, ah3, al3);
        const float2* Wr0 = Wsm + (ks * 8 + tig) * WS + cb;
        const float2* Wr1 = Wsm + (ks * 8 + tig + 4) * WS + cb;
        #pragma unroll
        for (int nt = 0; nt < NT; ++nt) {
            float2 w0 = Wr0[nt * 8 + gid];
            float2 w1 = Wr1[nt * 8 + gid];
            unsigned bh0 = __float_as_uint(w0.x), bl0 = __float_as_uint(w0.y);
            unsigned bh1 = __float_as_uint(w1.x), bl1 = __float_as_uint(w1.y);
            mma_f16(c[nt], ah0, ah1, ah2, ah3, bh0, bh1);   // Ah*Wh
            mma_f16(c[nt], al0, al1, al2, al3, bh0, bh1);   // Al*Wh
            mma_f16(c[nt], ah0, ah1, ah2, ah3, bl0, bl1);   // Ah*Wl
        }
    }
}

// 2-term mainloop for EXACT fp16 A (lo(A) == 0): D = A*Wh + A*Wl.
// A smem: unsigned half2-pairs, stride 68 (conflict-free fragment loads).
template <int NT, int WS>
__device__ __forceinline__ void tc_loop16(const unsigned* Asm16,
                                          const float2* Wsm,
                                          int r0, int gid, int tig,
                                          float (*c)[4]) {
    #pragma unroll
    for (int ks = 0; ks < 8; ++ks) {
        int kp = ks * 8;   // half2-pair base
        unsigned a0 = Asm16[(r0 + gid) * 68 + kp + tig];
        unsigned a1 = Asm16[(r0 + gid + 8) * 68 + kp + tig];
        unsigned a2 = Asm16[(r0 + gid) * 68 + kp + tig + 4];
        unsigned a3 = Asm16[(r0 + gid + 8) * 68 + kp + tig + 4];
        const float2* Wr0 = Wsm + (kp + tig) * WS;
        const float2* Wr1 = Wsm + (kp + tig + 4) * WS;
        #pragma unroll
        for (int nt = 0; nt < NT; ++nt) {
            float2 w0 = Wr0[nt * 8 + gid];
            float2 w1 = Wr1[nt * 8 + gid];
            unsigned bh0 = __float_as_uint(w0.x), bl0 = __float_as_uint(w0.y);
            unsigned bh1 = __float_as_uint(w1.x), bl1 = __float_as_uint(w1.y);
            mma_f16(c[nt], a0, a1, a2, a3, bh0, bh1);   // A*Wh
            mma_f16(c[nt], a0, a1, a2, a3, bl0, bl1);   // A*Wl
        }
    }
}

// ---------------------------------------------------------------------------
// Init (one launch): [0,196): zero counts + int-width detect; [196,278): prep
// ---------------------------------------------------------------------------
__global__ void k_init(const int* __restrict__ eiw,
                       const float* __restrict__ W1, const float* __restrict__ W2,
                       const float* __restrict__ Wout,
                       const float* __restrict__ b1, const float* __restrict__ b2) {
    int blk = blockIdx.x;
    int tid = threadIdx.x;
    if (blk < 196) {
        int i = blk * 256 + tid;
        if (i < NN) g_counts[i] = 0;
        // sticky detection: int64 little-endian has zero hi words; idempotent
        if (i < 4096 && eiw[2 * i + 1] != 0) g_is32 = 1;
    } else {
        int b = blk - 196;
        if (b < 64) {
            const float* W = (b < 32) ? W1 : W2;
            float2* O = (b < 32) ? g_Wp1 : g_Wp2;
            int idx = (b & 31) * 256 + tid;
            int pp = idx >> 7, n = idx & 127;
            int r0 = 2 * pp, r1 = 2 * pp + 1;
            float s0 = 0.f, s1 = 0.f;
            #pragma unroll 8
            for (int k = 0; k < DD; ++k) {
                float wc = W[k * DD + n];
                s0 += W[r0 * DD + k] * wc;
                s1 += W[r1 * DD + k] * wc;
            }
            O[idx] = pack_pair(s0, s1);
        } else if (b < 80) {
            int idx = (b - 64) * 256 + tid;
            int pp = idx >> 6, n = idx & 63;
            float w0 = Wout[(2 * pp) * OUTD + n];
            float w1 = Wout[(2 * pp + 1) * OUTD + n];
            g_WpO[idx] = pack_pair(w0, w1);
        } else {
            const float* bb = (b == 80) ? b1 : b2;
            const float* W  = (b == 80) ? W1 : W2;
            float* bw = (b == 80) ? g_bW1 : g_bW2;
            if (tid < DD) {
                float s = 0.f;
                #pragma unroll 8
                for (int k = 0; k < DD; ++k) s += bb[k] * W[k * DD + tid];
                bw[tid] = s;
            }
        }
    }
}

// Count in-degree AND record each edge's within-dst ordinal (the atomic's
// return value). Makes k_fill atomic-free.
__global__ void k_count(const void* __restrict__ ei) {
    int e = blockIdx.x * blockDim.x + threadIdx.x;
    if (e >= EE) return;
    int is32 = g_is32;
    int dst = load_edge(ei, EE + e, is32);
    if ((unsigned)dst < (unsigned)NN)
        g_ordinal[e] = atomicAdd(&g_counts[dst], 1);
}

// Self-summing scan: each block reduces counts[0 .. blockIdx*256) for its
// prefix (L2-resident), then local scan.
__global__ void k_rowoff() {
    __shared__ int ws[8];
    __shared__ int s_prefix;
    int tid = threadIdx.x;
    int lane = tid & 31, wid = tid >> 5;

    int lim = blockIdx.x * 256;
    int pi = 0;
    for (int j = tid; j < lim; j += 256) pi += g_counts[j];
    #pragma unroll
    for (int o = 16; o > 0; o >>= 1) pi += __shfl_down_sync(0xffffffffu, pi, o);
    if (lane == 0) ws[wid] = pi;
    __syncthreads();
    if (tid == 0) {
        int s = 0;
        #pragma unroll
        for (int w = 0; w < 8; ++w) s += ws[w];
        s_prefix = s;
    }
    __syncthreads();
    int prefix = s_prefix;
    __syncthreads();

    int i = blockIdx.x * 256 + tid;
    int v = (i < NN) ? g_counts[i] : 0;
    int x = v;
    #pragma unroll
    for (int o = 1; o < 32; o <<= 1) {
        int t = __shfl_up_sync(0xffffffffu, x, o);
        if (lane >= o) x += t;
    }
    if (lane == 31) ws[wid] = x;
    __syncthreads();
    if (wid == 0) {
        int y = (lane < 8) ? ws[lane] : 0;
        #pragma unroll
        for (int o = 1; o < 8; o <<= 1) {
            int t = __shfl_up_sync(0xffffffffu, y, o);
            if (lane >= o) y += t;
        }
        if (lane < 8) ws[lane] = y;
    }
    __syncthreads();
    int excl = x - v + (wid ? ws[wid - 1] : 0) + prefix;
    if (i < NN) {
        g_rowoff[i] = excl;
        g_deg[i] = (float)v;
        if (i == NN - 1) g_rowoff[NN] = excl + v;
    }
}

// Fill CSR — atomic-free (uses recorded ordinals).
__global__ void k_fill(const void* __restrict__ ei) {
    int e = blockIdx.x * blockDim.x + threadIdx.x;
    if (e >= EE) return;
    int is32 = g_is32;
    int src = load_edge(ei, e, is32);
    int dst = load_edge(ei, EE + e, is32);
    if ((unsigned)dst >= (unsigned)NN) return;
    if ((unsigned)src >= (unsigned)NN) src = 0;
    g_csrsrc[g_rowoff[dst] + g_ordinal[e]] = src;
}

// ---------------------------------------------------------------------------
// Aggregation over fp16 rows. One warp/node; lane owns 4 cols (uint2).
// ---------------------------------------------------------------------------
template <bool SDEG>
__device__ __forceinline__ float4 gather_row(const uint2* __restrict__ in,
                                             int node, int lane, float& sd) {
    float4 acc = make_float4(0.f, 0.f, 0.f, 0.f);
    int beg = g_rowoff[node], end = g_rowoff[node + 1];
    int e = beg;
    for (; e + 4 <= end; e += 4) {
        int s0 = g_csrsrc[e];
        int s1 = g_csrsrc[e + 1];
        int s2 = g_csrsrc[e + 2];
        int s3 = g_csrsrc[e + 3];
        uint2 u0 = in[(size_t)s0 * 32 + lane];
        uint2 u1 = in[(size_t)s1 * 32 + lane];
        uint2 u2 = in[(size_t)s2 * 32 + lane];
        uint2 u3 = in[(size_t)s3 * 32 + lane];
        if (SDEG) sd += (g_deg[s0] + g_deg[s1]) + (g_deg[s2] + g_deg[s3]);
        acc_add(acc, u0); acc_add(acc, u1);
        acc_add(acc, u2); acc_add(acc, u3);
    }
    for (; e < end; ++e) {
        int s0 = g_csrsrc[e];
        uint2 u0 = in[(size_t)s0 * 32 + lane];
        if (SDEG) sd += g_deg[s0];
        acc_add(acc, u0);
    }
    return acc;
}

// Plain gather -> fp16 (optionally computing sdeg on pass 1)
template <bool SDEG>
__global__ void __launch_bounds__(256) k_agg_hh(const uint2* __restrict__ in,
                                                uint2* __restrict__ out) {
    int w = (blockIdx.x * blockDim.x + threadIdx.x) >> 5;
    int lane = threadIdx.x & 31;
    if (w >= NN) return;
    float sd = 0.f;
    float4 acc = gather_row<SDEG>(in, w, lane, sd);
    __half2 h0 = __floats2half2_rn(acc.x, acc.y);
    __half2 h1 = __floats2half2_rn(acc.z, acc.w);
    uint2 o; o.x = h2_bits(h0); o.y = h2_bits(h1);
    out[(size_t)w * 32 + lane] = o;
    if (SDEG && lane == 0) g_sdeg[w] = sd;
}

// Gather + pool epilogue: h = relu(acc + sdeg*bw + deg*bv) -> fp16
__global__ void __launch_bounds__(256) k_agg_epi(const uint2* __restrict__ in,
                                                 const float* __restrict__ bw,
                                                 const float* __restrict__ bv,
                                                 uint2* __restrict__ out) {
    int w = (blockIdx.x * blockDim.x + threadIdx.x) >> 5;
    int lane = threadIdx.x & 31;
    if (w >= NN) return;
    float sd = 0.f;
    float4 acc = gather_row<false>(in, w, lane, sd);
    float s = g_sdeg[w], d = g_deg[w];
    float4 bw4 = ((const float4*)bw)[lane];
    float4 bv4 = ((const float4*)bv)[lane];
    acc.x = fmaxf(acc.x + s * bw4.x + d * bv4.x, 0.f);
    acc.y = fmaxf(acc.y + s * bw4.y + d * bv4.y, 0.f);
    acc.z = fmaxf(acc.z + s * bw4.z + d * bv4.z, 0.f);
    acc.w = fmaxf(acc.w + s * bw4.w + d * bv4.w, 0.f);
    __half2 h0 = __floats2half2_rn(acc.x, acc.y);
    __half2 h1 = __floats2half2_rn(acc.z, acc.w);
    uint2 o; o.x = h2_bits(h0); o.y = h2_bits(h1);
    out[(size_t)w * 32 + lane] = o;
}

// ---------------------------------------------------------------------------
// GEMM 1: z1 = x @ Wp1  (fp32 A, 3-term, no bias), fp16 out.
// 64 rows x 128 cols, 256 threads, 2 CTAs/SM.
// ---------------------------------------------------------------------------
__global__ void __launch_bounds__(256, 2)
k_gemm_x(const float* __restrict__ A, const float2* __restrict__ Wp,
         unsigned* __restrict__ C16) {
    extern __shared__ char smraw[];
    float*  Asm = (float*)smraw;                               // [64][132]
    float2* Wsm = (float2*)(smraw + 64 * 132 * sizeof(float)); // [64][132]

    const int tid = threadIdx.x;
    const int row0 = blockIdx.x * 64;

    #pragma unroll 4
    for (int idx = tid; idx < 64 * 128; idx += 256) {
        int p = idx >> 7, n = idx & 127;
        Wsm[p * 132 + n] = Wp[idx];
    }
    {
        const float4* Ag = (const float4*)A;
        #pragma unroll
        for (int it = 0; it < 8; ++it) {
            int idx = it * 256 + tid;
            int r = idx >> 5, kq = idx & 31;
            float4 v = make_float4(0.f, 0.f, 0.f, 0.f);
            if (row0 + r < NN) v = Ag[(size_t)(row0 + r) * 32 + kq];
            *(float4*)(Asm + r * 132 + kq * 4) = v;
        }
    }
    __syncthreads();

    const int warp = tid >> 5, lane = tid & 31;
    const int gid = lane >> 2, tig = lane & 3;
    const int r0 = (warp & 3) * 16;
    const int cb = (warp >> 2) * 64;   // float2-tile col base

    float c[8][4];
    #pragma unroll
    for (int nt = 0; nt < 8; ++nt)
        #pragma unroll
        for (int q = 0; q < 4; ++q) c[nt][q] = 0.f;

    tc_loop<8, 132>(Asm, Wsm, r0, cb, gid, tig, c);

    int rA = row0 + r0 + gid;
    int rB = rA + 8;
    #pragma unroll
    for (int nt = 0; nt < 8; ++nt) {
        int col = cb + nt * 8 + 2 * tig;
        if (rA < NN)
            C16[(size_t)rA * 64 + (col >> 1)] =
                h2_bits(__floats2half2_rn(c[nt][0], c[nt][1]));
        if (rB < NN)
            C16[(size_t)rB * 64 + (col >> 1)] =
                h2_bits(__floats2half2_rn(c[nt][2], c[nt][3]));
    }
}

// ---------------------------------------------------------------------------
// GEMM 2: z2 = h1 @ Wp2  (EXACT fp16 A, 2-term, no bias), fp16 out.
// 128 rows x 128 cols, 256 threads (8 warps x 16 rows), 2 CTAs/SM.
// ---------------------------------------------------------------------------
__global__ void __launch_bounds__(256, 2)
k_gemm_h(const uint2* __restrict__ A16, const float2* __restrict__ Wp,
         unsigned* __restrict__ C16) {
    extern __shared__ char smraw[];
    unsigned* Asm16 = (unsigned*)smraw;                          // [128][68]
    float2*   Wsm = (float2*)(smraw + 128 * 68 * sizeof(unsigned)); // [64][132]

    const int tid = threadIdx.x;
    const int row0 = blockIdx.x * 128;

    #pragma unroll 8
    for (int idx = tid; idx < 64 * 128; idx += 256) {
        int p = idx >> 7, n = idx & 127;
        Wsm[p * 132 + n] = Wp[idx];
    }
    {
        const uint4* Ag = (const uint4*)A16;   // 16 uint4 per 128-half row
        #pragma unroll
        for (int it = 0; it < 8; ++it) {
            int idx = it * 256 + tid;          // 0..2047
            int r = idx >> 4, q = idx & 15;
            uint4 v = make_uint4(0u, 0u, 0u, 0u);
            if (row0 + r < NN) v = Ag[(size_t)(row0 + r) * 16 + q];
            *(uint4*)(Asm16 + r * 68 + q * 4) = v;
        }
    }
    __syncthreads();

    const int warp = tid >> 5, lane = tid & 31;
    const int gid = lane >> 2, tig = lane & 3;
    const int r0 = warp * 16;

    float c[16][4];
    #pragma unroll
    for (int nt = 0; nt < 16; ++nt)
        #pragma unroll
        for (int q = 0; q < 4; ++q) c[nt][q] = 0.f;

    tc_loop16<16, 132>(Asm16, Wsm, r0, gid, tig, c);

    int rA = row0 + r0 + gid;
    int rB = rA + 8;
    #pragma unroll
    for (int nt = 0; nt < 16; ++nt) {
        int col = nt * 8 + 2 * tig;
        if (rA < NN)
            C16[(size_t)rA * 64 + (col >> 1)] =
                h2_bits(__floats2half2_rn(c[nt][0], c[nt][1]));
        if (rB < NN)
            C16[(size_t)rB * 64 + (col >> 1)] =
                h2_bits(__floats2half2_rn(c[nt][2], c[nt][3]));
    }
}

// ---------------------------------------------------------------------------
// GEMM out: out = h2 @ WpO + bout  (EXACT fp16 A, 2-term), fp32 out.
// 128 rows x 64 cols, 256 threads.
// ---------------------------------------------------------------------------
__global__ void __launch_bounds__(256, 2)
k_gemm_out(const uint2* __restrict__ A16, const float2* __restrict__ WpO,
           const float* __restrict__ bvo, float* __restrict__ out) {
    extern __shared__ char smraw[];
    unsigned* Asm16 = (unsigned*)smraw;                          // [128][68]
    float2*   Wsm = (float2*)(smraw + 128 * 68 * sizeof(unsigned)); // [64][68]

    const int tid = threadIdx.x;
    const int row0 = blockIdx.x * 128;

    #pragma unroll 4
    for (int idx = tid; idx < 64 * 64; idx += 256) {
        int p = idx >> 6, n = idx & 63;
        Wsm[p * 68 + n] = WpO[idx];
    }
    {
        const uint4* Ag = (const uint4*)A16;
        #pragma unroll
        for (int it = 0; it < 8; ++it) {
            int idx = it * 256 + tid;
            int r = idx >> 4, q = idx & 15;
            uint4 v = make_uint4(0u, 0u, 0u, 0u);
            if (row0 + r < NN) v = Ag[(size_t)(row0 + r) * 16 + q];
            *(uint4*)(Asm16 + r * 68 + q * 4) = v;
        }
    }
    __syncthreads();

    const int warp = tid >> 5, lane = tid & 31;
    const int gid = lane >> 2, tig = lane & 3;
    const int r0 = warp * 16;

    float c[8][4];
    #pragma unroll
    for (int nt = 0; nt < 8; ++nt)
        #pragma unroll
        for (int q = 0; q < 4; ++q) c[nt][q] = 0.f;

    tc_loop16<8, 68>(Asm16, Wsm, r0, gid, tig, c);

    int rA = row0 + r0 + gid;
    int rB = rA + 8;
    #pragma unroll
    for (int nt = 0; nt < 8; ++nt) {
        int col = nt * 8 + 2 * tig;
        float v0 = bvo[col], v1 = bvo[col + 1];
        if (rA < NN)
            *(float2*)&out[(size_t)rA * OUTD + col] =
                make_float2(c[nt][0] + v0, c[nt][1] + v1);
        if (rB < NN)
            *(float2*)&out[(size_t)rB * OUTD + col] =
                make_float2(c[nt][2] + v0, c[nt][3] + v1);
    }
}

// ---------------------------------------------------------------------------
// Launch: 11 kernels
// ---------------------------------------------------------------------------
extern "C" void kernel_launch(void* const* d_in, const int* in_sizes, int n_in,
                              void* d_out, int out_size) {
    const float* x    = (const float*)d_in[0];
    const void*  ei   = d_in[1];
    const float* W1   = (const float*)d_in[2];
    const float* b1   = (const float*)d_in[3];
    const float* W2   = (const float*)d_in[4];
    const float* b2   = (const float*)d_in[5];
    const float* Wout = (const float*)d_in[6];
    const float* bout = (const float*)d_in[7];
    float* out = (float*)d_out;

    void *pbW1, *pbW2, *pWp1, *pWp2, *pWpO, *pa, *pb, *pc;
    cudaGetSymbolAddress(&pbW1, g_bW1);
    cudaGetSymbolAddress(&pbW2, g_bW2);
    cudaGetSymbolAddress(&pWp1, g_Wp1);
    cudaGetSymbolAddress(&pWp2, g_Wp2);
    cudaGetSymbolAddress(&pWpO, g_WpO);
    cudaGetSymbolAddress(&pa, g_f16a);
    cudaGetSymbolAddress(&pb, g_f16b);
    cudaGetSymbolAddress(&pc, g_f16c);
    float*  bW1 = (float*)pbW1;
    float*  bW2 = (float*)pbW2;
    float2* Wp1 = (float2*)pWp1;
    float2* Wp2 = (float2*)pWp2;
    float2* WpO = (float2*)pWpO;
    uint2*  f16a = (uint2*)pa;
    uint2*  f16b = (uint2*)pb;
    uint2*  f16c = (uint2*)pc;

    const size_t SMX = 64 * 132 * sizeof(float) + 64 * 132 * sizeof(float2);    // ~99 KB
    const size_t SMH = 128 * 68 * sizeof(unsigned) + 64 * 132 * sizeof(float2); // 100 KB
    const size_t SMO = 128 * 68 * sizeof(unsigned) + 64 * 68 * sizeof(float2);  // ~68 KB
    cudaFuncSetAttribute(k_gemm_x,
                         cudaFuncAttributeMaxDynamicSharedMemorySize, (int)SMX);
    cudaFuncSetAttribute(k_gemm_h,
                         cudaFuncAttributeMaxDynamicSharedMemorySize, (int)SMH);
    cudaFuncSetAttribute(k_gemm_out,
                         cudaFuncAttributeMaxDynamicSharedMemorySize, (int)SMO);

    const int GE   = (EE + 255) / 256;
    const int GAG  = (NN * 32 + 255) / 256;   // one warp per node
    const int GGX  = (NN + 63) / 64;          // 782
    const int GGH  = (NN + 127) / 128;        // 391

    // ---- setup + CSR ----
    k_init<<<278, 256>>>((const int*)ei, W1, W2, Wout, b1, b2);
    k_count<<<GE, 256>>>(ei);
    k_rowoff<<<NB, 256>>>();
    k_fill<<<GE, 256>>>(ei);

    // ---- Block 1: h1 = relu(A^2(x@W1^2) + sdeg*(b1@W1) + deg*b1) ----
    k_gemm_x<<<GGX, 256, SMX>>>(x, Wp1, (unsigned*)f16a);     // z1
    k_agg_hh<true><<<GAG, 256>>>(f16a, f16b);                 // t = A(z1), sdeg
    k_agg_epi<<<GAG, 256>>>(f16b, bW1, b1, f16c);             // h1

    // ---- Block 2: h2 = relu(A^2(h1@W2^2) + sdeg*(b2@W2) + deg*b2) ----
    k_gemm_h<<<GGH, 256, SMH>>>(f16c, Wp2, (unsigned*)f16a);  // z2 (exact fp16)
    k_agg_hh<false><<<GAG, 256>>>(f16a, f16b);                // u = A(z2)
    k_agg_epi<<<GAG, 256>>>(f16b, bW2, b2, f16c);             // h2

    // ---- Output: out = h2 @ Wout + bout ----
    k_gemm_out<<<GGH, 256, SMO>>>(f16c, WpO, bout, out);
}